// round 7
// baseline (speedup 1.0000x reference)
#include <cuda_runtime.h>
#include <cuda_bf16.h>
#include <math.h>
#include <stdint.h>

// ---------------- scratch (device globals: no allocation allowed) ----------
__device__ float g_q[2048 * 4096];
__device__ float g_k[2048 * 1024];
__device__ float g_v[2048 * 1024];
__device__ float g_attn[2048 * 4096];
__device__ float g_cos[2048 * 64];
__device__ float g_sin[2048 * 64];

// ==================== shared helpers =======================================
__device__ __forceinline__ void mma16816(float acc[4], const uint32_t a[4],
                                         const uint32_t b[2]) {
    asm("mma.sync.aligned.m16n8k16.row.col.f32.bf16.bf16.f32 "
        "{%0,%1,%2,%3}, {%4,%5,%6,%7}, {%8,%9}, {%0,%1,%2,%3};\n"
        : "+f"(acc[0]), "+f"(acc[1]), "+f"(acc[2]), "+f"(acc[3])
        : "r"(a[0]), "r"(a[1]), "r"(a[2]), "r"(a[3]), "r"(b[0]), "r"(b[1]));
}

__device__ __forceinline__ void ldsm_x4(uint32_t& r0, uint32_t& r1,
                                        uint32_t& r2, uint32_t& r3,
                                        uint32_t addr) {
    asm volatile(
        "ldmatrix.sync.aligned.m8n8.x4.shared.b16 {%0,%1,%2,%3}, [%4];"
        : "=r"(r0), "=r"(r1), "=r"(r2), "=r"(r3) : "r"(addr));
}

__device__ __forceinline__ uint32_t smem_u32(const void* p) {
    uint32_t a;
    asm("{ .reg .u64 t; cvta.to.shared.u64 t, %1; cvt.u32.u64 %0, t; }"
        : "=r"(a) : "l"(p));
    return a;
}

__device__ __forceinline__ void split1(float x, __nv_bfloat16& hi, __nv_bfloat16& lo) {
    hi = __float2bfloat16(x);
    lo = __float2bfloat16(x - __bfloat162float(hi));
}

__device__ __forceinline__ void split2pack(float x, float y, uint32_t& hi, uint32_t& lo) {
    __nv_bfloat16 hx, lx, hy, ly;
    split1(x, hx, lx);
    split1(y, hy, ly);
    hi = ((uint32_t)__bfloat16_as_ushort(hy) << 16) | __bfloat16_as_ushort(hx);
    lo = ((uint32_t)__bfloat16_as_ushort(ly) << 16) | __bfloat16_as_ushort(lx);
}

// ==================== split-bf16 tensor-core GEMM (mma.sync) ===============
#define KPAD 40
#define TILE_HALFS (128 * KPAD)
#define BUF_HALFS (4 * TILE_HALFS)
#define GEMM_SMEM_BYTES (2 * BUF_HALFS * 2)

__global__ __launch_bounds__(256) void hgemm2(const float* __restrict__ A,
                                              const float* __restrict__ B,
                                              float* __restrict__ C,
                                              int M, int N, int K) {
    extern __shared__ __nv_bfloat16 smbuf[];

    const int tid = threadIdx.x;
    const int lane = tid & 31;
    const int w = tid >> 5;
    const int wm = w >> 1;
    const int wn = w & 1;
    const int g = lane >> 2;
    const int cc = lane & 3;
    const int quad = lane >> 3;
    const int qr = lane & 7;

    const float* Ab = A + (size_t)blockIdx.y * 128 * K;
    const float* Bb = B + (size_t)blockIdx.x * 128;

    const int lrow = (lane >> 2) + 8 * w;
    const int lkp = lane & 3;

    const uint32_t smbase = smem_u32(smbuf);

    float2 ra[2][4];
    float rb[2][4][2];

    auto load_gmem = [&](int k0) {
#pragma unroll
        for (int hf = 0; hf < 2; hf++)
#pragma unroll
            for (int rr = 0; rr < 4; rr++)
                ra[hf][rr] = *(const float2*)(Ab + (size_t)(lrow + 64 * hf) * K +
                                              k0 + 2 * (lkp + 4 * rr));
#pragma unroll
        for (int hf = 0; hf < 2; hf++)
#pragma unroll
            for (int rr = 0; rr < 4; rr++) {
                int krow = k0 + 2 * (lkp + 4 * rr);
                int n = lrow + 64 * hf;
                rb[hf][rr][0] = Bb[(size_t)krow * N + n];
                rb[hf][rr][1] = Bb[(size_t)(krow + 1) * N + n];
            }
    };

    auto store_smem = [&](int buf) {
        __nv_bfloat16* Ah = smbuf + buf * BUF_HALFS;
        __nv_bfloat16* Al = Ah + TILE_HALFS;
        __nv_bfloat16* Bh = Ah + 2 * TILE_HALFS;
        __nv_bfloat16* Bl = Ah + 3 * TILE_HALFS;
#pragma unroll
        for (int hf = 0; hf < 2; hf++)
#pragma unroll
            for (int rr = 0; rr < 4; rr++) {
                uint32_t h, l;
                split2pack(ra[hf][rr].x, ra[hf][rr].y, h, l);
                int off = (lrow + 64 * hf) * KPAD + 2 * (lkp + 4 * rr);
                *(uint32_t*)&Ah[off] = h;
                *(uint32_t*)&Al[off] = l;
            }
#pragma unroll
        for (int hf = 0; hf < 2; hf++)
#pragma unroll
            for (int rr = 0; rr < 4; rr++) {
                uint32_t h, l;
                split2pack(rb[hf][rr][0], rb[hf][rr][1], h, l);
                int off = (lrow + 64 * hf) * KPAD + 2 * (lkp + 4 * rr);
                *(uint32_t*)&Bh[off] = h;
                *(uint32_t*)&Bl[off] = l;
            }
    };

    float acc[2][8][4];
#pragma unroll
    for (int tm = 0; tm < 2; tm++)
#pragma unroll
        for (int tn = 0; tn < 8; tn++)
#pragma unroll
            for (int j = 0; j < 4; j++) acc[tm][tn][j] = 0.f;

    const uint32_t aLaneOff =
        (uint32_t)((wm * 32 + (quad & 1) * 8 + qr) * KPAD + (quad >> 1) * 8) * 2;
    const uint32_t bLaneOff =
        (uint32_t)((wn * 64 + (quad >> 1) * 8 + qr) * KPAD + (quad & 1) * 8) * 2;

    // pass-major mma tile: load ALL frags for a k-slice, then 3 passes of
    // 16 independent mma each (accumulator reuse distance = 16).
    auto mma_tile = [&](int buf) {
        const uint32_t sAh = smbase + buf * BUF_HALFS * 2;
        const uint32_t sAl = sAh + TILE_HALFS * 2;
        const uint32_t sBh = sAh + 2 * TILE_HALFS * 2;
        const uint32_t sBl = sAh + 3 * TILE_HALFS * 2;
#pragma unroll
        for (int ks = 0; ks < 32; ks += 16) {
            uint32_t ah[2][4], al[2][4];
#pragma unroll
            for (int tm = 0; tm < 2; tm++) {
                uint32_t off = aLaneOff + (uint32_t)(tm * 16 * KPAD + ks) * 2;
                ldsm_x4(ah[tm][0], ah[tm][1], ah[tm][2], ah[tm][3], sAh + off);
                ldsm_x4(al[tm][0], al[tm][1], al[tm][2], al[tm][3], sAl + off);
            }
            uint32_t bh[4][4], bl[4][4];
#pragma unroll
            for (int tp = 0; tp < 4; tp++) {
                uint32_t off = bLaneOff + (uint32_t)(tp * 16 * KPAD + ks) * 2;
                ldsm_x4(bh[tp][0], bh[tp][1], bh[tp][2], bh[tp][3], sBh + off);
                ldsm_x4(bl[tp][0], bl[tp][1], bl[tp][2], bl[tp][3], sBl + off);
            }
            // pass 1: hi*hi
#pragma unroll
            for (int tp = 0; tp < 4; tp++)
#pragma unroll
                for (int half = 0; half < 2; half++)
#pragma unroll
                    for (int tm = 0; tm < 2; tm++)
                        mma16816(acc[tm][tp * 2 + half], ah[tm], &bh[tp][half * 2]);
            // pass 2: hi*lo
#pragma unroll
            for (int tp = 0; tp < 4; tp++)
#pragma unroll
                for (int half = 0; half < 2; half++)
#pragma unroll
                    for (int tm = 0; tm < 2; tm++)
                        mma16816(acc[tm][tp * 2 + half], ah[tm], &bl[tp][half * 2]);
            // pass 3: lo*hi
#pragma unroll
            for (int tp = 0; tp < 4; tp++)
#pragma unroll
                for (int half = 0; half < 2; half++)
#pragma unroll
                    for (int tm = 0; tm < 2; tm++)
                        mma16816(acc[tm][tp * 2 + half], al[tm], &bh[tp][half * 2]);
        }
    };

    const int ntiles = K / 32;

    load_gmem(0);
    store_smem(0);
    load_gmem(32);
    __syncthreads();

    for (int t = 0; t < ntiles; t++) {
        mma_tile(t & 1);
        if (t + 1 < ntiles) {
            store_smem((t + 1) & 1);
            if (t + 2 < ntiles) load_gmem((t + 2) * 32);
        }
        __syncthreads();
    }

#pragma unroll
    for (int tm = 0; tm < 2; tm++) {
        int row0 = blockIdx.y * 128 + wm * 32 + tm * 16 + g;
#pragma unroll
        for (int tn = 0; tn < 8; tn++) {
            int col = blockIdx.x * 128 + wn * 64 + tn * 8 + 2 * cc;
            *(float2*)(C + (size_t)row0 * N + col) =
                make_float2(acc[tm][tn][0], acc[tm][tn][1]);
            *(float2*)(C + (size_t)(row0 + 8) * N + col) =
                make_float2(acc[tm][tn][2], acc[tm][tn][3]);
        }
    }
}

// ---------------- RoPE cos/sin table (fp64 for phase accuracy) -------------
__global__ void rope_table(const int* __restrict__ positions) {
    int idx = blockIdx.x * blockDim.x + threadIdx.x;
    if (idx >= 2048 * 64) return;
    int t = idx >> 6;
    int j = idx & 63;
    double inv = exp(-(double)j * (log(1.0e6) / 64.0));
    double f = (double)positions[t] * inv;
    g_cos[idx] = (float)cos(f);
    g_sin[idx] = (float)sin(f);
}

// ---------------- fused RMSNorm + RoPE for Q and K in one launch -----------
__global__ void rmsrope_both(float* __restrict__ Q, float* __restrict__ K,
                             const float* __restrict__ qw,
                             const float* __restrict__ kw) {
    int wg = (blockIdx.x * blockDim.x + threadIdx.x) >> 5;
    int lane = threadIdx.x & 31;

    float* x;
    int t;
    const float* w;
    if (wg < 2048 * 32) {
        t = wg >> 5;
        int h = wg & 31;
        x = Q + (size_t)t * 4096 + h * 128;
        w = qw;
    } else {
        int wg2 = wg - 2048 * 32;
        if (wg2 >= 2048 * 8) return;
        t = wg2 >> 3;
        int h = wg2 & 7;
        x = K + (size_t)t * 1024 + h * 128;
        w = kw;
    }

    float v0 = x[lane], v1 = x[lane + 32], v2 = x[lane + 64], v3 = x[lane + 96];
    float ss = v0 * v0 + v1 * v1 + v2 * v2 + v3 * v3;
#pragma unroll
    for (int off = 16; off > 0; off >>= 1) ss += __shfl_xor_sync(0xffffffffu, ss, off);
    float rms = rsqrtf(ss * (1.f / 128.f) + 1e-6f);

    v0 *= rms * w[lane];
    v1 *= rms * w[lane + 32];
    v2 *= rms * w[lane + 64];
    v3 *= rms * w[lane + 96];

    float c0 = g_cos[t * 64 + lane],      s0 = g_sin[t * 64 + lane];
    float c1 = g_cos[t * 64 + lane + 32], s1 = g_sin[t * 64 + lane + 32];

    x[lane]      = v0 * c0 - v2 * s0;
    x[lane + 64] = v2 * c0 + v0 * s0;
    x[lane + 32] = v1 * c1 - v3 * s1;
    x[lane + 96] = v3 * c1 + v1 * s1;
}

// ==================== tensor-core causal flash attention ===================
#define DPAD 136
#define VPAD 72
#define AQ_HALFS (128 * DPAD)
#define AK_HALFS (64 * DPAD)
#define AV_HALFS (128 * VPAD)
#define ATTN_SMEM_BYTES ((2 * AQ_HALFS + 2 * AK_HALFS + 2 * AV_HALFS) * 2)

__global__ __launch_bounds__(256) void attn_mma(const float* __restrict__ Q,
                                                const float* __restrict__ K,
                                                const float* __restrict__ V,
                                                float* __restrict__ O) {
    extern __shared__ __nv_bfloat16 asm_buf[];
    __nv_bfloat16* Qh = asm_buf;
    __nv_bfloat16* Ql = Qh + AQ_HALFS;
    __nv_bfloat16* Kh = Ql + AQ_HALFS;
    __nv_bfloat16* Kl = Kh + AK_HALFS;
    __nv_bfloat16* Vth = Kl + AK_HALFS;
    __nv_bfloat16* Vtl = Vth + AV_HALFS;

    const uint32_t sQh = smem_u32(Qh);
    const uint32_t sQl = smem_u32(Ql);
    const uint32_t sKh = smem_u32(Kh);
    const uint32_t sKl = smem_u32(Kl);
    const uint32_t sVh = smem_u32(Vth);
    const uint32_t sVl = smem_u32(Vtl);

    const int qbi = 15 - blockIdx.x;
    const int h = blockIdx.y;
    const int kvh = h >> 2;
    const int tid = threadIdx.x;
    const int lane = tid & 31;
    const int w = tid >> 5;
    const int g = lane >> 2;
    const int cc = lane & 3;
    const int quad = lane >> 3;
    const int qr = lane & 7;

    const int ntiles = 2 * (qbi + 1);
    const float scale = 0.08838834764831845f;

    // ---- load Q block (128 x 128), split hi/lo ----
    {
        const int row = tid >> 1;
        const int half = tid & 1;
        const float* qp = Q + (size_t)(qbi * 128 + row) * 4096 + h * 128 + half * 64;
#pragma unroll
        for (int i = 0; i < 32; i++) {
            float2 v = *(const float2*)(qp + 2 * i);
            uint32_t hh, ll;
            split2pack(v.x, v.y, hh, ll);
            int off = row * DPAD + half * 64 + 2 * i;
            *(uint32_t*)&Qh[off] = hh;
            *(uint32_t*)&Ql[off] = ll;
        }
    }

    const uint32_t aQOff =
        (uint32_t)((w * 16 + (quad & 1) * 8 + qr) * DPAD + (quad >> 1) * 8) * 2;
    const uint32_t bKOff =
        (uint32_t)(((quad >> 1) * 8 + qr) * DPAD + (quad & 1) * 8) * 2;
    const uint32_t bVOff =
        (uint32_t)(((quad >> 1) * 8 + qr) * VPAD + (quad & 1) * 8) * 2;

    float oacc[16][4];
#pragma unroll
    for (int tn = 0; tn < 16; tn++)
#pragma unroll
        for (int j = 0; j < 4; j++) oacc[tn][j] = 0.f;

    float mA = -1e30f, mB = -1e30f, lA = 0.f, lB = 0.f;
    const int rowA = qbi * 128 + w * 16 + g;
    const int rowB = rowA + 8;

    __syncthreads();

    for (int kb = 0; kb < ntiles; kb++) {
        // ---- load K tile ----
        {
            const int kv = tid >> 2;
            const int j = tid & 3;
            const float* kp = K + (size_t)(kb * 64 + kv) * 1024 + kvh * 128;
#pragma unroll
            for (int i = 0; i < 16; i++) {
                int d0 = 2 * (j + 4 * i);
                float2 v = *(const float2*)(kp + d0);
                uint32_t hh, ll;
                split2pack(v.x, v.y, hh, ll);
                int off = kv * DPAD + d0;
                *(uint32_t*)&Kh[off] = hh;
                *(uint32_t*)&Kl[off] = ll;
            }
        }
        // ---- load V tile transposed ----
        {
            const int d = tid & 127;
            const int half = tid >> 7;
            const float* vp = V + (size_t)(kb * 64) * 1024 + kvh * 128 + d;
#pragma unroll
            for (int i = 0; i < 16; i++) {
                int kp2 = half * 16 + i;
                float v0 = vp[(size_t)(2 * kp2) * 1024];
                float v1 = vp[(size_t)(2 * kp2 + 1) * 1024];
                uint32_t hh, ll;
                split2pack(v0, v1, hh, ll);
                int off = d * VPAD + 2 * kp2;
                *(uint32_t*)&Vth[off] = hh;
                *(uint32_t*)&Vtl[off] = ll;
            }
        }
        __syncthreads();

        // ---- S = Q K^T, pass-major (reuse distance 8) ----
        float sacc[8][4];
#pragma unroll
        for (int tn = 0; tn < 8; tn++)
#pragma unroll
            for (int j = 0; j < 4; j++) sacc[tn][j] = 0.f;

#pragma unroll
        for (int ks = 0; ks < 128; ks += 16) {
            uint32_t ah[4], al[4];
            uint32_t aoff = aQOff + (uint32_t)ks * 2;
            ldsm_x4(ah[0], ah[1], ah[2], ah[3], sQh + aoff);
            ldsm_x4(al[0], al[1], al[2], al[3], sQl + aoff);
            uint32_t bh[4][4], bl[4][4];
#pragma unroll
            for (int p = 0; p < 4; p++) {
                uint32_t boff = bKOff + (uint32_t)(p * 16 * DPAD + ks) * 2;
                ldsm_x4(bh[p][0], bh[p][1], bh[p][2], bh[p][3], sKh + boff);
                ldsm_x4(bl[p][0], bl[p][1], bl[p][2], bl[p][3], sKl + boff);
            }
#pragma unroll
            for (int p = 0; p < 4; p++)
#pragma unroll
                for (int half = 0; half < 2; half++)
                    mma16816(sacc[2 * p + half], ah, &bh[p][half * 2]);
#pragma unroll
            for (int p = 0; p < 4; p++)
#pragma unroll
                for (int half = 0; half < 2; half++)
                    mma16816(sacc[2 * p + half], ah, &bl[p][half * 2]);
#pragma unroll
            for (int p = 0; p < 4; p++)
#pragma unroll
                for (int half = 0; half < 2; half++)
                    mma16816(sacc[2 * p + half], al, &bh[p][half * 2]);
        }

        // ---- softmax on fragments ----
        float mxA = -1e30f, mxB = -1e30f;
#pragma unroll
        for (int tn = 0; tn < 8; tn++) {
            int colbase = kb * 64 + tn * 8 + 2 * cc;
            float s0 = sacc[tn][0] * scale;
            float s1 = sacc[tn][1] * scale;
            float s2 = sacc[tn][2] * scale;
            float s3 = sacc[tn][3] * scale;
            if (colbase > rowA) s0 = -1e30f;
            if (colbase + 1 > rowA) s1 = -1e30f;
            if (colbase > rowB) s2 = -1e30f;
            if (colbase + 1 > rowB) s3 = -1e30f;
            sacc[tn][0] = s0; sacc[tn][1] = s1;
            sacc[tn][2] = s2; sacc[tn][3] = s3;
            mxA = fmaxf(mxA, fmaxf(s0, s1));
            mxB = fmaxf(mxB, fmaxf(s2, s3));
        }
        mxA = fmaxf(mxA, __shfl_xor_sync(0xffffffffu, mxA, 1));
        mxA = fmaxf(mxA, __shfl_xor_sync(0xffffffffu, mxA, 2));
        mxB = fmaxf(mxB, __shfl_xor_sync(0xffffffffu, mxB, 1));
        mxB = fmaxf(mxB, __shfl_xor_sync(0xffffffffu, mxB, 2));

        float mnA = fmaxf(mA, mxA);
        float mnB = fmaxf(mB, mxB);
        float corrA = __expf(mA - mnA);
        float corrB = __expf(mB - mnB);
        mA = mnA;
        mB = mnB;

        float sumA = 0.f, sumB = 0.f;
#pragma unroll
        for (int tn = 0; tn < 8; tn++) {
            float p0 = __expf(sacc[tn][0] - mnA);
            float p1 = __expf(sacc[tn][1] - mnA);
            float p2 = __expf(sacc[tn][2] - mnB);
            float p3 = __expf(sacc[tn][3] - mnB);
            sacc[tn][0] = p0; sacc[tn][1] = p1;
            sacc[tn][2] = p2; sacc[tn][3] = p3;
            sumA += p0 + p1;
            sumB += p2 + p3;
        }
        sumA += __shfl_xor_sync(0xffffffffu, sumA, 1);
        sumA += __shfl_xor_sync(0xffffffffu, sumA, 2);
        sumB += __shfl_xor_sync(0xffffffffu, sumB, 1);
        sumB += __shfl_xor_sync(0xffffffffu, sumB, 2);
        lA = lA * corrA + sumA;
        lB = lB * corrB + sumB;

#pragma unroll
        for (int tn = 0; tn < 16; tn++) {
            oacc[tn][0] *= corrA;
            oacc[tn][1] *= corrA;
            oacc[tn][2] *= corrB;
            oacc[tn][3] *= corrB;
        }

        // ---- O += P V, p-pairs, pass-major within pair (reuse dist 4) ----
#pragma unroll
        for (int j = 0; j < 4; j++) {
            uint32_t pah[4], pal[4];
            split2pack(sacc[2 * j][0], sacc[2 * j][1], pah[0], pal[0]);
            split2pack(sacc[2 * j][2], sacc[2 * j][3], pah[1], pal[1]);
            split2pack(sacc[2 * j + 1][0], sacc[2 * j + 1][1], pah[2], pal[2]);
            split2pack(sacc[2 * j + 1][2], sacc[2 * j + 1][3], pah[3], pal[3]);
#pragma unroll
            for (int pp = 0; pp < 4; pp++) {
                uint32_t bh[2][4], bl[2][4];
#pragma unroll
                for (int i = 0; i < 2; i++) {
                    uint32_t voff = bVOff +
                        (uint32_t)((2 * pp + i) * 16 * VPAD + j * 16) * 2;
                    ldsm_x4(bh[i][0], bh[i][1], bh[i][2], bh[i][3], sVh + voff);
                    ldsm_x4(bl[i][0], bl[i][1], bl[i][2], bl[i][3], sVl + voff);
                }
#pragma unroll
                for (int i = 0; i < 2; i++)
#pragma unroll
                    for (int half = 0; half < 2; half++)
                        mma16816(oacc[2 * (2 * pp + i) + half], pah, &bh[i][half * 2]);
#pragma unroll
                for (int i = 0; i < 2; i++)
#pragma unroll
                    for (int half = 0; half < 2; half++)
                        mma16816(oacc[2 * (2 * pp + i) + half], pah, &bl[i][half * 2]);
#pragma unroll
                for (int i = 0; i < 2; i++)
#pragma unroll
                    for (int half = 0; half < 2; half++)
                        mma16816(oacc[2 * (2 * pp + i) + half], pal, &bh[i][half * 2]);
            }
        }
        __syncthreads();
    }

    // ---- epilogue ----
    const float invA = 1.f / lA;
    const float invB = 1.f / lB;
#pragma unroll
    for (int tn = 0; tn < 16; tn++) {
        int d = tn * 8 + 2 * cc;
        *(float2*)(O + (size_t)rowA * 4096 + h * 128 + d) =
            make_float2(oacc[tn][0] * invA, oacc[tn][1] * invA);
        *(float2*)(O + (size_t)rowB * 4096 + h * 128 + d) =
            make_float2(oacc[tn][2] * invB, oacc[tn][3] * invB);
    }
}

// ---------------- launch ----------------------------------------------------
extern "C" void kernel_launch(void* const* d_in, const int* in_sizes, int n_in,
                              void* d_out, int out_size) {
    const float* hidden    = (const float*)d_in[0];
    const int*   positions = (const int*)d_in[1];
    const float* Wq        = (const float*)d_in[2];
    const float* Wk        = (const float*)d_in[3];
    const float* Wv        = (const float*)d_in[4];
    const float* Wo        = (const float*)d_in[5];
    const float* q_norm_w  = (const float*)d_in[6];
    const float* k_norm_w  = (const float*)d_in[7];
    float* out = (float*)d_out;

    float* q;    cudaGetSymbolAddress((void**)&q, g_q);
    float* k;    cudaGetSymbolAddress((void**)&k, g_k);
    float* v;    cudaGetSymbolAddress((void**)&v, g_v);
    float* attn; cudaGetSymbolAddress((void**)&attn, g_attn);

    cudaFuncSetAttribute(hgemm2, cudaFuncAttributeMaxDynamicSharedMemorySize,
                         GEMM_SMEM_BYTES);
    cudaFuncSetAttribute(attn_mma, cudaFuncAttributeMaxDynamicSharedMemorySize,
                         ATTN_SMEM_BYTES);

    // 1: rope table
    rope_table<<<(2048 * 64 + 255) / 256, 256>>>(positions);

    // 2-4: QKV projections
    hgemm2<<<dim3(32, 16), 256, GEMM_SMEM_BYTES>>>(hidden, Wq, q, 2048, 4096, 4096);
    hgemm2<<<dim3(8, 16), 256, GEMM_SMEM_BYTES>>>(hidden, Wk, k, 2048, 1024, 4096);
    hgemm2<<<dim3(8, 16), 256, GEMM_SMEM_BYTES>>>(hidden, Wv, v, 2048, 1024, 4096);

    // 5: fused rmsnorm+rope
    rmsrope_both<<<(2048 * 40) / 8, 256>>>(q, k, q_norm_w, k_norm_w);

    // 6: attention (tensor cores)
    attn_mma<<<dim3(16, 32), 256, ATTN_SMEM_BYTES>>>(q, k, v, attn);

    // 7: output projection
    hgemm2<<<dim3(32, 16), 256, GEMM_SMEM_BYTES>>>(attn, Wo, out, 2048, 4096, 4096);
}

// round 8
// speedup vs baseline: 1.4774x; 1.4774x over previous
#include <cuda_runtime.h>
#include <cuda_bf16.h>
#include <cuda_fp16.h>
#include <math.h>
#include <stdint.h>

// ---------------- scratch (device globals: no allocation allowed) ----------
__device__ float g_q[2048 * 4096];
__device__ float g_k[2048 * 1024];
__device__ float g_v[2048 * 1024];
__device__ float g_attn[2048 * 4096];
__device__ float g_cos[2048 * 64];
__device__ float g_sin[2048 * 64];

// ==================== shared helpers =======================================
__device__ __forceinline__ void mma16816(float acc[4], const uint32_t a[4],
                                         const uint32_t b[2]) {
    asm("mma.sync.aligned.m16n8k16.row.col.f32.f16.f16.f32 "
        "{%0,%1,%2,%3}, {%4,%5,%6,%7}, {%8,%9}, {%0,%1,%2,%3};\n"
        : "+f"(acc[0]), "+f"(acc[1]), "+f"(acc[2]), "+f"(acc[3])
        : "r"(a[0]), "r"(a[1]), "r"(a[2]), "r"(a[3]), "r"(b[0]), "r"(b[1]));
}

__device__ __forceinline__ void ldsm_x4(uint32_t& r0, uint32_t& r1,
                                        uint32_t& r2, uint32_t& r3,
                                        uint32_t addr) {
    asm volatile(
        "ldmatrix.sync.aligned.m8n8.x4.shared.b16 {%0,%1,%2,%3}, [%4];"
        : "=r"(r0), "=r"(r1), "=r"(r2), "=r"(r3) : "r"(addr));
}

__device__ __forceinline__ uint32_t smem_u32(const void* p) {
    uint32_t a;
    asm("{ .reg .u64 t; cvta.to.shared.u64 t, %1; cvt.u32.u64 %0, t; }"
        : "=r"(a) : "l"(p));
    return a;
}

// fp16 exact split: x = hi + lo to ~24 bits
__device__ __forceinline__ void splitA2(float x, float y, uint32_t& hi, uint32_t& lo) {
    __half hx = __float2half_rn(x);
    __half hy = __float2half_rn(y);
    __half lx = __float2half_rn(x - __half2float(hx));
    __half ly = __float2half_rn(y - __half2float(hy));
    __half2 h = __halves2half2(hx, hy);
    __half2 l = __halves2half2(lx, ly);
    hi = *(uint32_t*)&h;
    lo = *(uint32_t*)&l;
}

__device__ __forceinline__ uint32_t pack2h(float x, float y) {
    __half2 h = __floats2half2_rn(x, y);
    return *(uint32_t*)&h;
}

// ==================== fp16 2-pass tensor-core GEMM =========================
// C = A@B fp32 gmem. A split hi/lo (exact), B rounded to fp16.
// acc = ah*bh + al*bh. BM=BN=128, BK=32, 8 warps (4x2), warp tile 32x64.
#define KPAD 40
#define TILE_HALFS (128 * KPAD)
#define BUF_HALFS (3 * TILE_HALFS)         // Ah, Al, Bh
#define GEMM_SMEM_BYTES (2 * BUF_HALFS * 2)

__global__ __launch_bounds__(256) void hgemm2(const float* __restrict__ A,
                                              const float* __restrict__ B,
                                              float* __restrict__ C,
                                              int M, int N, int K) {
    extern __shared__ __half smbuf[];

    const int tid = threadIdx.x;
    const int lane = tid & 31;
    const int w = tid >> 5;
    const int wm = w >> 1;
    const int wn = w & 1;
    const int g = lane >> 2;
    const int cc = lane & 3;
    const int quad = lane >> 3;
    const int qr = lane & 7;

    const float* Ab = A + (size_t)blockIdx.y * 128 * K;
    const float* Bb = B + (size_t)blockIdx.x * 128;

    const int lrow = (lane >> 2) + 8 * w;
    const int lkp = lane & 3;

    const uint32_t smbase = smem_u32(smbuf);

    float2 ra[2][4];
    float rb[2][4][2];

    auto load_gmem = [&](int k0) {
#pragma unroll
        for (int hf = 0; hf < 2; hf++)
#pragma unroll
            for (int rr = 0; rr < 4; rr++)
                ra[hf][rr] = *(const float2*)(Ab + (size_t)(lrow + 64 * hf) * K +
                                              k0 + 2 * (lkp + 4 * rr));
#pragma unroll
        for (int hf = 0; hf < 2; hf++)
#pragma unroll
            for (int rr = 0; rr < 4; rr++) {
                int krow = k0 + 2 * (lkp + 4 * rr);
                int n = lrow + 64 * hf;
                rb[hf][rr][0] = Bb[(size_t)krow * N + n];
                rb[hf][rr][1] = Bb[(size_t)(krow + 1) * N + n];
            }
    };

    auto store_smem = [&](int buf) {
        __half* Ah = smbuf + buf * BUF_HALFS;
        __half* Al = Ah + TILE_HALFS;
        __half* Bh = Ah + 2 * TILE_HALFS;
#pragma unroll
        for (int hf = 0; hf < 2; hf++)
#pragma unroll
            for (int rr = 0; rr < 4; rr++) {
                uint32_t h, l;
                splitA2(ra[hf][rr].x, ra[hf][rr].y, h, l);
                int off = (lrow + 64 * hf) * KPAD + 2 * (lkp + 4 * rr);
                *(uint32_t*)&Ah[off] = h;
                *(uint32_t*)&Al[off] = l;
            }
#pragma unroll
        for (int hf = 0; hf < 2; hf++)
#pragma unroll
            for (int rr = 0; rr < 4; rr++) {
                int off = (lrow + 64 * hf) * KPAD + 2 * (lkp + 4 * rr);
                *(uint32_t*)&Bh[off] = pack2h(rb[hf][rr][0], rb[hf][rr][1]);
            }
    };

    float acc[2][8][4];
#pragma unroll
    for (int tm = 0; tm < 2; tm++)
#pragma unroll
        for (int tn = 0; tn < 8; tn++)
#pragma unroll
            for (int j = 0; j < 4; j++) acc[tm][tn][j] = 0.f;

    const uint32_t aLaneOff =
        (uint32_t)((wm * 32 + (quad & 1) * 8 + qr) * KPAD + (quad >> 1) * 8) * 2;
    const uint32_t bLaneOff =
        (uint32_t)((wn * 64 + (quad >> 1) * 8 + qr) * KPAD + (quad & 1) * 8) * 2;

    auto mma_tile = [&](int buf) {
        const uint32_t sAh = smbase + buf * BUF_HALFS * 2;
        const uint32_t sAl = sAh + TILE_HALFS * 2;
        const uint32_t sBh = sAh + 2 * TILE_HALFS * 2;
#pragma unroll
        for (int ks = 0; ks < 32; ks += 16) {
            uint32_t ah[2][4], al[2][4];
#pragma unroll
            for (int tm = 0; tm < 2; tm++) {
                uint32_t off = aLaneOff + (uint32_t)(tm * 16 * KPAD + ks) * 2;
                ldsm_x4(ah[tm][0], ah[tm][1], ah[tm][2], ah[tm][3], sAh + off);
                ldsm_x4(al[tm][0], al[tm][1], al[tm][2], al[tm][3], sAl + off);
            }
            uint32_t bh[4][4];
#pragma unroll
            for (int tp = 0; tp < 4; tp++) {
                uint32_t off = bLaneOff + (uint32_t)(tp * 16 * KPAD + ks) * 2;
                ldsm_x4(bh[tp][0], bh[tp][1], bh[tp][2], bh[tp][3], sBh + off);
            }
            // pass 1: a_hi * b
#pragma unroll
            for (int tp = 0; tp < 4; tp++)
#pragma unroll
                for (int half = 0; half < 2; half++)
#pragma unroll
                    for (int tm = 0; tm < 2; tm++)
                        mma16816(acc[tm][tp * 2 + half], ah[tm], &bh[tp][half * 2]);
            // pass 2: a_lo * b
#pragma unroll
            for (int tp = 0; tp < 4; tp++)
#pragma unroll
                for (int half = 0; half < 2; half++)
#pragma unroll
                    for (int tm = 0; tm < 2; tm++)
                        mma16816(acc[tm][tp * 2 + half], al[tm], &bh[tp][half * 2]);
        }
    };

    const int ntiles = K / 32;

    load_gmem(0);
    store_smem(0);
    load_gmem(32);
    __syncthreads();

    for (int t = 0; t < ntiles; t++) {
        mma_tile(t & 1);
        if (t + 1 < ntiles) {
            store_smem((t + 1) & 1);
            if (t + 2 < ntiles) load_gmem((t + 2) * 32);
        }
        __syncthreads();
    }

#pragma unroll
    for (int tm = 0; tm < 2; tm++) {
        int row0 = blockIdx.y * 128 + wm * 32 + tm * 16 + g;
#pragma unroll
        for (int tn = 0; tn < 8; tn++) {
            int col = blockIdx.x * 128 + wn * 64 + tn * 8 + 2 * cc;
            *(float2*)(C + (size_t)row0 * N + col) =
                make_float2(acc[tm][tn][0], acc[tm][tn][1]);
            *(float2*)(C + (size_t)(row0 + 8) * N + col) =
                make_float2(acc[tm][tn][2], acc[tm][tn][3]);
        }
    }
}

// ---------------- RoPE cos/sin table (fp64 for phase accuracy) -------------
__global__ void rope_table(const int* __restrict__ positions) {
    int idx = blockIdx.x * blockDim.x + threadIdx.x;
    if (idx >= 2048 * 64) return;
    int t = idx >> 6;
    int j = idx & 63;
    double inv = exp(-(double)j * (log(1.0e6) / 64.0));
    double f = (double)positions[t] * inv;
    g_cos[idx] = (float)cos(f);
    g_sin[idx] = (float)sin(f);
}

// ---------------- fused RMSNorm + RoPE for Q and K in one launch -----------
__global__ void rmsrope_both(float* __restrict__ Q, float* __restrict__ K,
                             const float* __restrict__ qw,
                             const float* __restrict__ kw) {
    int wg = (blockIdx.x * blockDim.x + threadIdx.x) >> 5;
    int lane = threadIdx.x & 31;

    float* x;
    int t;
    const float* w;
    if (wg < 2048 * 32) {
        t = wg >> 5;
        int h = wg & 31;
        x = Q + (size_t)t * 4096 + h * 128;
        w = qw;
    } else {
        int wg2 = wg - 2048 * 32;
        if (wg2 >= 2048 * 8) return;
        t = wg2 >> 3;
        int h = wg2 & 7;
        x = K + (size_t)t * 1024 + h * 128;
        w = kw;
    }

    float v0 = x[lane], v1 = x[lane + 32], v2 = x[lane + 64], v3 = x[lane + 96];
    float ss = v0 * v0 + v1 * v1 + v2 * v2 + v3 * v3;
#pragma unroll
    for (int off = 16; off > 0; off >>= 1) ss += __shfl_xor_sync(0xffffffffu, ss, off);
    float rms = rsqrtf(ss * (1.f / 128.f) + 1e-6f);

    v0 *= rms * w[lane];
    v1 *= rms * w[lane + 32];
    v2 *= rms * w[lane + 64];
    v3 *= rms * w[lane + 96];

    float c0 = g_cos[t * 64 + lane],      s0 = g_sin[t * 64 + lane];
    float c1 = g_cos[t * 64 + lane + 32], s1 = g_sin[t * 64 + lane + 32];

    x[lane]      = v0 * c0 - v2 * s0;
    x[lane + 64] = v2 * c0 + v0 * s0;
    x[lane + 32] = v1 * c1 - v3 * s1;
    x[lane + 96] = v3 * c1 + v1 * s1;
}

// ==================== tensor-core causal flash attention ===================
// Q split hi/lo (exact), K fp16 hi only; P split hi/lo, V fp16 hi only.
#define DPAD 136
#define VPAD 72
#define AQ_HALFS (128 * DPAD)
#define AK_HALFS (64 * DPAD)
#define AV_HALFS (128 * VPAD)
#define ATTN_SMEM_BYTES ((2 * AQ_HALFS + AK_HALFS + AV_HALFS) * 2)

__global__ __launch_bounds__(256) void attn_mma(const float* __restrict__ Q,
                                                const float* __restrict__ K,
                                                const float* __restrict__ V,
                                                float* __restrict__ O) {
    extern __shared__ __half asm_buf[];
    __half* Qh = asm_buf;
    __half* Ql = Qh + AQ_HALFS;
    __half* Kh = Ql + AQ_HALFS;
    __half* Vth = Kh + AK_HALFS;

    const uint32_t sQh = smem_u32(Qh);
    const uint32_t sQl = smem_u32(Ql);
    const uint32_t sKh = smem_u32(Kh);
    const uint32_t sVh = smem_u32(Vth);

    const int qbi = 15 - blockIdx.x;
    const int h = blockIdx.y;
    const int kvh = h >> 2;
    const int tid = threadIdx.x;
    const int lane = tid & 31;
    const int w = tid >> 5;
    const int g = lane >> 2;
    const int cc = lane & 3;
    const int quad = lane >> 3;
    const int qr = lane & 7;

    const int ntiles = 2 * (qbi + 1);
    const float scale = 0.08838834764831845f;

    // ---- load Q block (128 x 128), split hi/lo ----
    {
        const int row = tid >> 1;
        const int half = tid & 1;
        const float* qp = Q + (size_t)(qbi * 128 + row) * 4096 + h * 128 + half * 64;
#pragma unroll
        for (int i = 0; i < 32; i++) {
            float2 v = *(const float2*)(qp + 2 * i);
            uint32_t hh, ll;
            splitA2(v.x, v.y, hh, ll);
            int off = row * DPAD + half * 64 + 2 * i;
            *(uint32_t*)&Qh[off] = hh;
            *(uint32_t*)&Ql[off] = ll;
        }
    }

    const uint32_t aQOff =
        (uint32_t)((w * 16 + (quad & 1) * 8 + qr) * DPAD + (quad >> 1) * 8) * 2;
    const uint32_t bKOff =
        (uint32_t)(((quad >> 1) * 8 + qr) * DPAD + (quad & 1) * 8) * 2;
    const uint32_t bVOff =
        (uint32_t)(((quad >> 1) * 8 + qr) * VPAD + (quad & 1) * 8) * 2;

    float oacc[16][4];
#pragma unroll
    for (int tn = 0; tn < 16; tn++)
#pragma unroll
        for (int j = 0; j < 4; j++) oacc[tn][j] = 0.f;

    float mA = -1e30f, mB = -1e30f, lA = 0.f, lB = 0.f;
    const int rowA = qbi * 128 + w * 16 + g;
    const int rowB = rowA + 8;

    __syncthreads();

    for (int kb = 0; kb < ntiles; kb++) {
        // ---- load K tile (hi only) ----
        {
            const int kv = tid >> 2;
            const int j = tid & 3;
            const float* kp = K + (size_t)(kb * 64 + kv) * 1024 + kvh * 128;
#pragma unroll
            for (int i = 0; i < 16; i++) {
                int d0 = 2 * (j + 4 * i);
                float2 v = *(const float2*)(kp + d0);
                *(uint32_t*)&Kh[kv * DPAD + d0] = pack2h(v.x, v.y);
            }
        }
        // ---- load V tile transposed (hi only) ----
        {
            const int d = tid & 127;
            const int half = tid >> 7;
            const float* vp = V + (size_t)(kb * 64) * 1024 + kvh * 128 + d;
#pragma unroll
            for (int i = 0; i < 16; i++) {
                int kp2 = half * 16 + i;
                float v0 = vp[(size_t)(2 * kp2) * 1024];
                float v1 = vp[(size_t)(2 * kp2 + 1) * 1024];
                *(uint32_t*)&Vth[d * VPAD + 2 * kp2] = pack2h(v0, v1);
            }
        }
        __syncthreads();

        // ---- S = Q K^T, 2-pass ----
        float sacc[8][4];
#pragma unroll
        for (int tn = 0; tn < 8; tn++)
#pragma unroll
            for (int j = 0; j < 4; j++) sacc[tn][j] = 0.f;

#pragma unroll
        for (int ks = 0; ks < 128; ks += 16) {
            uint32_t ah[4], al[4];
            uint32_t aoff = aQOff + (uint32_t)ks * 2;
            ldsm_x4(ah[0], ah[1], ah[2], ah[3], sQh + aoff);
            ldsm_x4(al[0], al[1], al[2], al[3], sQl + aoff);
            uint32_t bh[4][4];
#pragma unroll
            for (int p = 0; p < 4; p++) {
                uint32_t boff = bKOff + (uint32_t)(p * 16 * DPAD + ks) * 2;
                ldsm_x4(bh[p][0], bh[p][1], bh[p][2], bh[p][3], sKh + boff);
            }
#pragma unroll
            for (int p = 0; p < 4; p++)
#pragma unroll
                for (int half = 0; half < 2; half++)
                    mma16816(sacc[2 * p + half], ah, &bh[p][half * 2]);
#pragma unroll
            for (int p = 0; p < 4; p++)
#pragma unroll
                for (int half = 0; half < 2; half++)
                    mma16816(sacc[2 * p + half], al, &bh[p][half * 2]);
        }

        // ---- softmax on fragments ----
        float mxA = -1e30f, mxB = -1e30f;
#pragma unroll
        for (int tn = 0; tn < 8; tn++) {
            int colbase = kb * 64 + tn * 8 + 2 * cc;
            float s0 = sacc[tn][0] * scale;
            float s1 = sacc[tn][1] * scale;
            float s2 = sacc[tn][2] * scale;
            float s3 = sacc[tn][3] * scale;
            if (colbase > rowA) s0 = -1e30f;
            if (colbase + 1 > rowA) s1 = -1e30f;
            if (colbase > rowB) s2 = -1e30f;
            if (colbase + 1 > rowB) s3 = -1e30f;
            sacc[tn][0] = s0; sacc[tn][1] = s1;
            sacc[tn][2] = s2; sacc[tn][3] = s3;
            mxA = fmaxf(mxA, fmaxf(s0, s1));
            mxB = fmaxf(mxB, fmaxf(s2, s3));
        }
        mxA = fmaxf(mxA, __shfl_xor_sync(0xffffffffu, mxA, 1));
        mxA = fmaxf(mxA, __shfl_xor_sync(0xffffffffu, mxA, 2));
        mxB = fmaxf(mxB, __shfl_xor_sync(0xffffffffu, mxB, 1));
        mxB = fmaxf(mxB, __shfl_xor_sync(0xffffffffu, mxB, 2));

        float mnA = fmaxf(mA, mxA);
        float mnB = fmaxf(mB, mxB);
        float corrA = __expf(mA - mnA);
        float corrB = __expf(mB - mnB);
        mA = mnA;
        mB = mnB;

        float sumA = 0.f, sumB = 0.f;
#pragma unroll
        for (int tn = 0; tn < 8; tn++) {
            float p0 = __expf(sacc[tn][0] - mnA);
            float p1 = __expf(sacc[tn][1] - mnA);
            float p2 = __expf(sacc[tn][2] - mnB);
            float p3 = __expf(sacc[tn][3] - mnB);
            sacc[tn][0] = p0; sacc[tn][1] = p1;
            sacc[tn][2] = p2; sacc[tn][3] = p3;
            sumA += p0 + p1;
            sumB += p2 + p3;
        }
        sumA += __shfl_xor_sync(0xffffffffu, sumA, 1);
        sumA += __shfl_xor_sync(0xffffffffu, sumA, 2);
        sumB += __shfl_xor_sync(0xffffffffu, sumB, 1);
        sumB += __shfl_xor_sync(0xffffffffu, sumB, 2);
        lA = lA * corrA + sumA;
        lB = lB * corrB + sumB;

#pragma unroll
        for (int tn = 0; tn < 16; tn++) {
            oacc[tn][0] *= corrA;
            oacc[tn][1] *= corrA;
            oacc[tn][2] *= corrB;
            oacc[tn][3] *= corrB;
        }

        // ---- O += P V, 2-pass (P exact, V hi only) ----
#pragma unroll
        for (int j = 0; j < 4; j++) {
            uint32_t pah[4], pal[4];
            splitA2(sacc[2 * j][0], sacc[2 * j][1], pah[0], pal[0]);
            splitA2(sacc[2 * j][2], sacc[2 * j][3], pah[1], pal[1]);
            splitA2(sacc[2 * j + 1][0], sacc[2 * j + 1][1], pah[2], pal[2]);
            splitA2(sacc[2 * j + 1][2], sacc[2 * j + 1][3], pah[3], pal[3]);
#pragma unroll
            for (int pp = 0; pp < 4; pp++) {
                uint32_t bh[2][4];
#pragma unroll
                for (int i = 0; i < 2; i++) {
                    uint32_t voff = bVOff +
                        (uint32_t)((2 * pp + i) * 16 * VPAD + j * 16) * 2;
                    ldsm_x4(bh[i][0], bh[i][1], bh[i][2], bh[i][3], sVh + voff);
                }
#pragma unroll
                for (int i = 0; i < 2; i++)
#pragma unroll
                    for (int half = 0; half < 2; half++)
                        mma16816(oacc[2 * (2 * pp + i) + half], pah, &bh[i][half * 2]);
#pragma unroll
                for (int i = 0; i < 2; i++)
#pragma unroll
                    for (int half = 0; half < 2; half++)
                        mma16816(oacc[2 * (2 * pp + i) + half], pal, &bh[i][half * 2]);
            }
        }
        __syncthreads();
    }

    // ---- epilogue ----
    const float invA = 1.f / lA;
    const float invB = 1.f / lB;
#pragma unroll
    for (int tn = 0; tn < 16; tn++) {
        int d = tn * 8 + 2 * cc;
        *(float2*)(O + (size_t)rowA * 4096 + h * 128 + d) =
            make_float2(oacc[tn][0] * invA, oacc[tn][1] * invA);
        *(float2*)(O + (size_t)rowB * 4096 + h * 128 + d) =
            make_float2(oacc[tn][2] * invB, oacc[tn][3] * invB);
    }
}

// ---------------- launch ----------------------------------------------------
extern "C" void kernel_launch(void* const* d_in, const int* in_sizes, int n_in,
                              void* d_out, int out_size) {
    const float* hidden    = (const float*)d_in[0];
    const int*   positions = (const int*)d_in[1];
    const float* Wq        = (const float*)d_in[2];
    const float* Wk        = (const float*)d_in[3];
    const float* Wv        = (const float*)d_in[4];
    const float* Wo        = (const float*)d_in[5];
    const float* q_norm_w  = (const float*)d_in[6];
    const float* k_norm_w  = (const float*)d_in[7];
    float* out = (float*)d_out;

    float* q;    cudaGetSymbolAddress((void**)&q, g_q);
    float* k;    cudaGetSymbolAddress((void**)&k, g_k);
    float* v;    cudaGetSymbolAddress((void**)&v, g_v);
    float* attn; cudaGetSymbolAddress((void**)&attn, g_attn);

    cudaFuncSetAttribute(hgemm2, cudaFuncAttributeMaxDynamicSharedMemorySize,
                         GEMM_SMEM_BYTES);
    cudaFuncSetAttribute(attn_mma, cudaFuncAttributeMaxDynamicSharedMemorySize,
                         ATTN_SMEM_BYTES);

    // 1: rope table
    rope_table<<<(2048 * 64 + 255) / 256, 256>>>(positions);

    // 2-4: QKV projections
    hgemm2<<<dim3(32, 16), 256, GEMM_SMEM_BYTES>>>(hidden, Wq, q, 2048, 4096, 4096);
    hgemm2<<<dim3(8, 16), 256, GEMM_SMEM_BYTES>>>(hidden, Wk, k, 2048, 1024, 4096);
    hgemm2<<<dim3(8, 16), 256, GEMM_SMEM_BYTES>>>(hidden, Wv, v, 2048, 1024, 4096);

    // 5: fused rmsnorm+rope
    rmsrope_both<<<(2048 * 40) / 8, 256>>>(q, k, q_norm_w, k_norm_w);

    // 6: attention (tensor cores)
    attn_mma<<<dim3(16, 32), 256, ATTN_SMEM_BYTES>>>(q, k, v, attn);

    // 7: output projection
    hgemm2<<<dim3(32, 16), 256, GEMM_SMEM_BYTES>>>(attn, Wo, out, 2048, 4096, 4096);
}

// round 9
// speedup vs baseline: 1.7468x; 1.1823x over previous
#include <cuda_runtime.h>
#include <cuda_fp16.h>
#include <math.h>
#include <stdint.h>

// ---------------- scratch (device globals: no allocation allowed) ----------
__device__ float g_q[2048 * 4096];
__device__ float g_k[2048 * 1024];
__device__ float g_v[2048 * 1024];
__device__ float g_cos[2048 * 64];
__device__ float g_sin[2048 * 64];
// fp16 pre-converted operands
__device__ __half g_wqt[4096 * 4096];   // Wq^T [N][K]
__device__ __half g_wkt[1024 * 4096];
__device__ __half g_wvt[1024 * 4096];
__device__ __half g_wot[4096 * 4096];   // Wo^T
__device__ __half g_hh[2048 * 4096];    // hidden hi
__device__ __half g_hl[2048 * 4096];    // hidden lo
__device__ __half g_oh[2048 * 4096];    // attn out hi
__device__ __half g_ol[2048 * 4096];    // attn out lo

// ==================== shared helpers =======================================
__device__ __forceinline__ void mma16816(float acc[4], const uint32_t a[4],
                                         const uint32_t b[2]) {
    asm("mma.sync.aligned.m16n8k16.row.col.f32.f16.f16.f32 "
        "{%0,%1,%2,%3}, {%4,%5,%6,%7}, {%8,%9}, {%0,%1,%2,%3};\n"
        : "+f"(acc[0]), "+f"(acc[1]), "+f"(acc[2]), "+f"(acc[3])
        : "r"(a[0]), "r"(a[1]), "r"(a[2]), "r"(a[3]), "r"(b[0]), "r"(b[1]));
}

__device__ __forceinline__ void ldsm_x4(uint32_t& r0, uint32_t& r1,
                                        uint32_t& r2, uint32_t& r3,
                                        uint32_t addr) {
    asm volatile(
        "ldmatrix.sync.aligned.m8n8.x4.shared.b16 {%0,%1,%2,%3}, [%4];"
        : "=r"(r0), "=r"(r1), "=r"(r2), "=r"(r3) : "r"(addr));
}

__device__ __forceinline__ uint32_t smem_u32(const void* p) {
    uint32_t a;
    asm("{ .reg .u64 t; cvta.to.shared.u64 t, %1; cvt.u32.u64 %0, t; }"
        : "=r"(a) : "l"(p));
    return a;
}

__device__ __forceinline__ void cp16(uint32_t smem, const void* g) {
    asm volatile("cp.async.cg.shared.global [%0], [%1], 16;\n"
                 :: "r"(smem), "l"(g) : "memory");
}
#define CP_COMMIT asm volatile("cp.async.commit_group;\n" ::: "memory")
#define CP_WAIT1 asm volatile("cp.async.wait_group 1;\n" ::: "memory")

// fp16 exact split: x = hi + lo (~24 bits)
__device__ __forceinline__ void splitA2(float x, float y, uint32_t& hi, uint32_t& lo) {
    __half hx = __float2half_rn(x);
    __half hy = __float2half_rn(y);
    __half lx = __float2half_rn(x - __half2float(hx));
    __half ly = __float2half_rn(y - __half2float(hy));
    __half2 h = __halves2half2(hx, hy);
    __half2 l = __halves2half2(lx, ly);
    hi = *(uint32_t*)&h;
    lo = *(uint32_t*)&l;
}

__device__ __forceinline__ uint32_t pack2h(float x, float y) {
    __half2 h = __floats2half2_rn(x, y);
    return *(uint32_t*)&h;
}

// ==================== conversion kernels ===================================
// W [K][N] fp32 -> Wt [N][K] fp16 (transpose + round)
__global__ void convert_w(const float* __restrict__ W, __half* __restrict__ Wt,
                          int K, int N) {
    __shared__ float t[32][33];
    int n0 = blockIdx.x * 32, k0 = blockIdx.y * 32;
    int tx = threadIdx.x, ty = threadIdx.y;   // 32 x 8
#pragma unroll
    for (int i = 0; i < 32; i += 8)
        t[ty + i][tx] = W[(size_t)(k0 + ty + i) * N + n0 + tx];
    __syncthreads();
#pragma unroll
    for (int i = 0; i < 32; i += 8)
        Wt[(size_t)(n0 + ty + i) * K + k0 + tx] = __float2half_rn(t[tx][ty + i]);
}

// hidden fp32 -> hi/lo fp16
__global__ void split_hidden(const float* __restrict__ H, __half* __restrict__ Hh,
                             __half* __restrict__ Hl, int n) {
    int i = (blockIdx.x * blockDim.x + threadIdx.x) * 2;
    if (i >= n) return;
    float2 v = *(const float2*)(H + i);
    uint32_t h, l;
    splitA2(v.x, v.y, h, l);
    *(uint32_t*)(Hh + i) = h;
    *(uint32_t*)(Hl + i) = l;
}

// ==================== fp16 cp.async tensor-core GEMM =======================
// C = (Ah+Al)@Bt^T, all fp16 inputs. BM=BN=128, BK=32, 8 warps (4x2),
// warp tile 32x64, double-buffered cp.async, 2 CTAs/SM target.
#define KPAD 40
#define TILE_HALFS (128 * KPAD)
#define BUF3 (3 * TILE_HALFS)              // Ah, Al, B
#define GEMM_SMEM_BYTES (2 * BUF3 * 2)

__global__ __launch_bounds__(256, 2) void hgemm3(const __half* __restrict__ Ah,
                                                 const __half* __restrict__ Al,
                                                 const __half* __restrict__ Bt,
                                                 float* __restrict__ C,
                                                 int M, int N, int K) {
    extern __shared__ __half smbuf[];

    const int tid = threadIdx.x;
    const int lane = tid & 31;
    const int w = tid >> 5;
    const int wm = w >> 1;
    const int wn = w & 1;
    const int g = lane >> 2;
    const int cc = lane & 3;
    const int quad = lane >> 3;
    const int qr = lane & 7;

    const __half* Abh = Ah + (size_t)blockIdx.y * 128 * K;
    const __half* Abl = Al + (size_t)blockIdx.y * 128 * K;
    const __half* Bb = Bt + (size_t)blockIdx.x * 128 * K;

    const uint32_t smbase = smem_u32(smbuf);

    // copy mapping: thread -> (row, 32B segment)
    const int crow = tid >> 1;
    const int cseg = (tid & 1) * 32;

    auto issue = [&](int buf, int k0) {
        uint32_t dst = smbase + buf * BUF3 * 2 + crow * 80 + cseg;
        const char* sa = (const char*)(Abh + (size_t)crow * K + k0) + cseg;
        cp16(dst, sa);
        cp16(dst + 16, sa + 16);
        const char* sl = (const char*)(Abl + (size_t)crow * K + k0) + cseg;
        cp16(dst + TILE_HALFS * 2, sl);
        cp16(dst + TILE_HALFS * 2 + 16, sl + 16);
        const char* sb = (const char*)(Bb + (size_t)crow * K + k0) + cseg;
        cp16(dst + 2 * TILE_HALFS * 2, sb);
        cp16(dst + 2 * TILE_HALFS * 2 + 16, sb + 16);
    };

    float acc[2][8][4];
#pragma unroll
    for (int tm = 0; tm < 2; tm++)
#pragma unroll
        for (int tn = 0; tn < 8; tn++)
#pragma unroll
            for (int j = 0; j < 4; j++) acc[tm][tn][j] = 0.f;

    const uint32_t aLaneOff =
        (uint32_t)((wm * 32 + (quad & 1) * 8 + qr) * KPAD + (quad >> 1) * 8) * 2;
    const uint32_t bLaneOff =
        (uint32_t)((wn * 64 + (quad >> 1) * 8 + qr) * KPAD + (quad & 1) * 8) * 2;

    auto mma_tile = [&](int buf) {
        const uint32_t sAh = smbase + buf * BUF3 * 2;
        const uint32_t sAl = sAh + TILE_HALFS * 2;
        const uint32_t sBh = sAh + 2 * TILE_HALFS * 2;
#pragma unroll
        for (int ks = 0; ks < 32; ks += 16) {
            uint32_t ah[2][4], al[2][4];
#pragma unroll
            for (int tm = 0; tm < 2; tm++) {
                uint32_t off = aLaneOff + (uint32_t)(tm * 16 * KPAD + ks) * 2;
                ldsm_x4(ah[tm][0], ah[tm][1], ah[tm][2], ah[tm][3], sAh + off);
                ldsm_x4(al[tm][0], al[tm][1], al[tm][2], al[tm][3], sAl + off);
            }
            uint32_t bh[4][4];
#pragma unroll
            for (int tp = 0; tp < 4; tp++) {
                uint32_t off = bLaneOff + (uint32_t)(tp * 16 * KPAD + ks) * 2;
                ldsm_x4(bh[tp][0], bh[tp][1], bh[tp][2], bh[tp][3], sBh + off);
            }
#pragma unroll
            for (int tp = 0; tp < 4; tp++)
#pragma unroll
                for (int half = 0; half < 2; half++)
#pragma unroll
                    for (int tm = 0; tm < 2; tm++)
                        mma16816(acc[tm][tp * 2 + half], ah[tm], &bh[tp][half * 2]);
#pragma unroll
            for (int tp = 0; tp < 4; tp++)
#pragma unroll
                for (int half = 0; half < 2; half++)
#pragma unroll
                    for (int tm = 0; tm < 2; tm++)
                        mma16816(acc[tm][tp * 2 + half], al[tm], &bh[tp][half * 2]);
        }
    };

    const int ntiles = K / 32;

    issue(0, 0);
    CP_COMMIT;
    issue(1, 32);
    CP_COMMIT;

    for (int t = 0; t < ntiles; t++) {
        CP_WAIT1;
        __syncthreads();
        mma_tile(t & 1);
        __syncthreads();
        if (t + 2 < ntiles) issue(t & 1, (t + 2) * 32);
        CP_COMMIT;           // always commit (possibly empty) to keep counting
    }

#pragma unroll
    for (int tm = 0; tm < 2; tm++) {
        int row0 = blockIdx.y * 128 + wm * 32 + tm * 16 + g;
#pragma unroll
        for (int tn = 0; tn < 8; tn++) {
            int col = blockIdx.x * 128 + wn * 64 + tn * 8 + 2 * cc;
            *(float2*)(C + (size_t)row0 * N + col) =
                make_float2(acc[tm][tn][0], acc[tm][tn][1]);
            *(float2*)(C + (size_t)(row0 + 8) * N + col) =
                make_float2(acc[tm][tn][2], acc[tm][tn][3]);
        }
    }
}

// ---------------- RoPE cos/sin table (fp64 for phase accuracy) -------------
__global__ void rope_table(const int* __restrict__ positions) {
    int idx = blockIdx.x * blockDim.x + threadIdx.x;
    if (idx >= 2048 * 64) return;
    int t = idx >> 6;
    int j = idx & 63;
    double inv = exp(-(double)j * (log(1.0e6) / 64.0));
    double f = (double)positions[t] * inv;
    g_cos[idx] = (float)cos(f);
    g_sin[idx] = (float)sin(f);
}

// ---------------- fused RMSNorm + RoPE for Q and K in one launch -----------
__global__ void rmsrope_both(float* __restrict__ Q, float* __restrict__ K,
                             const float* __restrict__ qw,
                             const float* __restrict__ kw) {
    int wg = (blockIdx.x * blockDim.x + threadIdx.x) >> 5;
    int lane = threadIdx.x & 31;

    float* x;
    int t;
    const float* w;
    if (wg < 2048 * 32) {
        t = wg >> 5;
        int h = wg & 31;
        x = Q + (size_t)t * 4096 + h * 128;
        w = qw;
    } else {
        int wg2 = wg - 2048 * 32;
        if (wg2 >= 2048 * 8) return;
        t = wg2 >> 3;
        int h = wg2 & 7;
        x = K + (size_t)t * 1024 + h * 128;
        w = kw;
    }

    float v0 = x[lane], v1 = x[lane + 32], v2 = x[lane + 64], v3 = x[lane + 96];
    float ss = v0 * v0 + v1 * v1 + v2 * v2 + v3 * v3;
#pragma unroll
    for (int off = 16; off > 0; off >>= 1) ss += __shfl_xor_sync(0xffffffffu, ss, off);
    float rms = rsqrtf(ss * (1.f / 128.f) + 1e-6f);

    v0 *= rms * w[lane];
    v1 *= rms * w[lane + 32];
    v2 *= rms * w[lane + 64];
    v3 *= rms * w[lane + 96];

    float c0 = g_cos[t * 64 + lane],      s0 = g_sin[t * 64 + lane];
    float c1 = g_cos[t * 64 + lane + 32], s1 = g_sin[t * 64 + lane + 32];

    x[lane]      = v0 * c0 - v2 * s0;
    x[lane + 64] = v2 * c0 + v0 * s0;
    x[lane + 32] = v1 * c1 - v3 * s1;
    x[lane + 96] = v3 * c1 + v1 * s1;
}

// ==================== tensor-core causal flash attention ===================
// Q split hi/lo (exact), K fp16 hi only; P split hi/lo, V fp16 hi only.
// Epilogue emits O as fp16 hi/lo split (feeds the O-projection directly).
#define DPAD 136
#define VPAD 72
#define AQ_HALFS (128 * DPAD)
#define AK_HALFS (64 * DPAD)
#define AV_HALFS (128 * VPAD)
#define ATTN_SMEM_BYTES ((2 * AQ_HALFS + AK_HALFS + AV_HALFS) * 2)

__global__ __launch_bounds__(256) void attn_mma(const float* __restrict__ Q,
                                                const float* __restrict__ K,
                                                const float* __restrict__ V,
                                                __half* __restrict__ Oh,
                                                __half* __restrict__ Ol) {
    extern __shared__ __half asm_buf[];
    __half* Qh = asm_buf;
    __half* Ql = Qh + AQ_HALFS;
    __half* Kh = Ql + AQ_HALFS;
    __half* Vth = Kh + AK_HALFS;

    const uint32_t sQh = smem_u32(Qh);
    const uint32_t sQl = smem_u32(Ql);
    const uint32_t sKh = smem_u32(Kh);
    const uint32_t sVh = smem_u32(Vth);

    const int qbi = 15 - blockIdx.x;
    const int h = blockIdx.y;
    const int kvh = h >> 2;
    const int tid = threadIdx.x;
    const int lane = tid & 31;
    const int w = tid >> 5;
    const int g = lane >> 2;
    const int cc = lane & 3;
    const int quad = lane >> 3;
    const int qr = lane & 7;

    const int ntiles = 2 * (qbi + 1);
    const float scale = 0.08838834764831845f;

    // ---- load Q block (128 x 128), split hi/lo ----
    {
        const int row = tid >> 1;
        const int half = tid & 1;
        const float* qp = Q + (size_t)(qbi * 128 + row) * 4096 + h * 128 + half * 64;
#pragma unroll
        for (int i = 0; i < 32; i++) {
            float2 v = *(const float2*)(qp + 2 * i);
            uint32_t hh, ll;
            splitA2(v.x, v.y, hh, ll);
            int off = row * DPAD + half * 64 + 2 * i;
            *(uint32_t*)&Qh[off] = hh;
            *(uint32_t*)&Ql[off] = ll;
        }
    }

    const uint32_t aQOff =
        (uint32_t)((w * 16 + (quad & 1) * 8 + qr) * DPAD + (quad >> 1) * 8) * 2;
    const uint32_t bKOff =
        (uint32_t)(((quad >> 1) * 8 + qr) * DPAD + (quad & 1) * 8) * 2;
    const uint32_t bVOff =
        (uint32_t)(((quad >> 1) * 8 + qr) * VPAD + (quad & 1) * 8) * 2;

    float oacc[16][4];
#pragma unroll
    for (int tn = 0; tn < 16; tn++)
#pragma unroll
        for (int j = 0; j < 4; j++) oacc[tn][j] = 0.f;

    float mA = -1e30f, mB = -1e30f, lA = 0.f, lB = 0.f;
    const int rowA = qbi * 128 + w * 16 + g;
    const int rowB = rowA + 8;

    __syncthreads();

    for (int kb = 0; kb < ntiles; kb++) {
        // ---- load K tile (hi only) ----
        {
            const int kv = tid >> 2;
            const int j = tid & 3;
            const float* kp = K + (size_t)(kb * 64 + kv) * 1024 + kvh * 128;
#pragma unroll
            for (int i = 0; i < 16; i++) {
                int d0 = 2 * (j + 4 * i);
                float2 v = *(const float2*)(kp + d0);
                *(uint32_t*)&Kh[kv * DPAD + d0] = pack2h(v.x, v.y);
            }
        }
        // ---- load V tile transposed (hi only) ----
        {
            const int d = tid & 127;
            const int half = tid >> 7;
            const float* vp = V + (size_t)(kb * 64) * 1024 + kvh * 128 + d;
#pragma unroll
            for (int i = 0; i < 16; i++) {
                int kp2 = half * 16 + i;
                float v0 = vp[(size_t)(2 * kp2) * 1024];
                float v1 = vp[(size_t)(2 * kp2 + 1) * 1024];
                *(uint32_t*)&Vth[d * VPAD + 2 * kp2] = pack2h(v0, v1);
            }
        }
        __syncthreads();

        // ---- S = Q K^T, 2-pass ----
        float sacc[8][4];
#pragma unroll
        for (int tn = 0; tn < 8; tn++)
#pragma unroll
            for (int j = 0; j < 4; j++) sacc[tn][j] = 0.f;

#pragma unroll
        for (int ks = 0; ks < 128; ks += 16) {
            uint32_t ah[4], al[4];
            uint32_t aoff = aQOff + (uint32_t)ks * 2;
            ldsm_x4(ah[0], ah[1], ah[2], ah[3], sQh + aoff);
            ldsm_x4(al[0], al[1], al[2], al[3], sQl + aoff);
            uint32_t bh[4][4];
#pragma unroll
            for (int p = 0; p < 4; p++) {
                uint32_t boff = bKOff + (uint32_t)(p * 16 * DPAD + ks) * 2;
                ldsm_x4(bh[p][0], bh[p][1], bh[p][2], bh[p][3], sKh + boff);
            }
#pragma unroll
            for (int p = 0; p < 4; p++)
#pragma unroll
                for (int half = 0; half < 2; half++)
                    mma16816(sacc[2 * p + half], ah, &bh[p][half * 2]);
#pragma unroll
            for (int p = 0; p < 4; p++)
#pragma unroll
                for (int half = 0; half < 2; half++)
                    mma16816(sacc[2 * p + half], al, &bh[p][half * 2]);
        }

        // ---- softmax on fragments ----
        float mxA = -1e30f, mxB = -1e30f;
#pragma unroll
        for (int tn = 0; tn < 8; tn++) {
            int colbase = kb * 64 + tn * 8 + 2 * cc;
            float s0 = sacc[tn][0] * scale;
            float s1 = sacc[tn][1] * scale;
            float s2 = sacc[tn][2] * scale;
            float s3 = sacc[tn][3] * scale;
            if (colbase > rowA) s0 = -1e30f;
            if (colbase + 1 > rowA) s1 = -1e30f;
            if (colbase > rowB) s2 = -1e30f;
            if (colbase + 1 > rowB) s3 = -1e30f;
            sacc[tn][0] = s0; sacc[tn][1] = s1;
            sacc[tn][2] = s2; sacc[tn][3] = s3;
            mxA = fmaxf(mxA, fmaxf(s0, s1));
            mxB = fmaxf(mxB, fmaxf(s2, s3));
        }
        mxA = fmaxf(mxA, __shfl_xor_sync(0xffffffffu, mxA, 1));
        mxA = fmaxf(mxA, __shfl_xor_sync(0xffffffffu, mxA, 2));
        mxB = fmaxf(mxB, __shfl_xor_sync(0xffffffffu, mxB, 1));
        mxB = fmaxf(mxB, __shfl_xor_sync(0xffffffffu, mxB, 2));

        float mnA = fmaxf(mA, mxA);
        float mnB = fmaxf(mB, mxB);
        float corrA = __expf(mA - mnA);
        float corrB = __expf(mB - mnB);
        mA = mnA;
        mB = mnB;

        float sumA = 0.f, sumB = 0.f;
#pragma unroll
        for (int tn = 0; tn < 8; tn++) {
            float p0 = __expf(sacc[tn][0] - mnA);
            float p1 = __expf(sacc[tn][1] - mnA);
            float p2 = __expf(sacc[tn][2] - mnB);
            float p3 = __expf(sacc[tn][3] - mnB);
            sacc[tn][0] = p0; sacc[tn][1] = p1;
            sacc[tn][2] = p2; sacc[tn][3] = p3;
            sumA += p0 + p1;
            sumB += p2 + p3;
        }
        sumA += __shfl_xor_sync(0xffffffffu, sumA, 1);
        sumA += __shfl_xor_sync(0xffffffffu, sumA, 2);
        sumB += __shfl_xor_sync(0xffffffffu, sumB, 1);
        sumB += __shfl_xor_sync(0xffffffffu, sumB, 2);
        lA = lA * corrA + sumA;
        lB = lB * corrB + sumB;

#pragma unroll
        for (int tn = 0; tn < 16; tn++) {
            oacc[tn][0] *= corrA;
            oacc[tn][1] *= corrA;
            oacc[tn][2] *= corrB;
            oacc[tn][3] *= corrB;
        }

        // ---- O += P V, 2-pass (P exact, V hi only) ----
#pragma unroll
        for (int j = 0; j < 4; j++) {
            uint32_t pah[4], pal[4];
            splitA2(sacc[2 * j][0], sacc[2 * j][1], pah[0], pal[0]);
            splitA2(sacc[2 * j][2], sacc[2 * j][3], pah[1], pal[1]);
            splitA2(sacc[2 * j + 1][0], sacc[2 * j + 1][1], pah[2], pal[2]);
            splitA2(sacc[2 * j + 1][2], sacc[2 * j + 1][3], pah[3], pal[3]);
#pragma unroll
            for (int pp = 0; pp < 4; pp++) {
                uint32_t bh[2][4];
#pragma unroll
                for (int i = 0; i < 2; i++) {
                    uint32_t voff = bVOff +
                        (uint32_t)((2 * pp + i) * 16 * VPAD + j * 16) * 2;
                    ldsm_x4(bh[i][0], bh[i][1], bh[i][2], bh[i][3], sVh + voff);
                }
#pragma unroll
                for (int i = 0; i < 2; i++)
#pragma unroll
                    for (int half = 0; half < 2; half++)
                        mma16816(oacc[2 * (2 * pp + i) + half], pah, &bh[i][half * 2]);
#pragma unroll
                for (int i = 0; i < 2; i++)
#pragma unroll
                    for (int half = 0; half < 2; half++)
                        mma16816(oacc[2 * (2 * pp + i) + half], pal, &bh[i][half * 2]);
            }
        }
        __syncthreads();
    }

    // ---- epilogue: write O as fp16 hi/lo split ----
    const float invA = 1.f / lA;
    const float invB = 1.f / lB;
#pragma unroll
    for (int tn = 0; tn < 16; tn++) {
        int d = tn * 8 + 2 * cc;
        uint32_t hh, ll;
        splitA2(oacc[tn][0] * invA, oacc[tn][1] * invA, hh, ll);
        *(uint32_t*)(Oh + (size_t)rowA * 4096 + h * 128 + d) = hh;
        *(uint32_t*)(Ol + (size_t)rowA * 4096 + h * 128 + d) = ll;
        splitA2(oacc[tn][2] * invB, oacc[tn][3] * invB, hh, ll);
        *(uint32_t*)(Oh + (size_t)rowB * 4096 + h * 128 + d) = hh;
        *(uint32_t*)(Ol + (size_t)rowB * 4096 + h * 128 + d) = ll;
    }
}

// ---------------- launch ----------------------------------------------------
extern "C" void kernel_launch(void* const* d_in, const int* in_sizes, int n_in,
                              void* d_out, int out_size) {
    const float* hidden    = (const float*)d_in[0];
    const int*   positions = (const int*)d_in[1];
    const float* Wq        = (const float*)d_in[2];
    const float* Wk        = (const float*)d_in[3];
    const float* Wv        = (const float*)d_in[4];
    const float* Wo        = (const float*)d_in[5];
    const float* q_norm_w  = (const float*)d_in[6];
    const float* k_norm_w  = (const float*)d_in[7];
    float* out = (float*)d_out;

    float* q;  cudaGetSymbolAddress((void**)&q, g_q);
    float* k;  cudaGetSymbolAddress((void**)&k, g_k);
    float* v;  cudaGetSymbolAddress((void**)&v, g_v);
    __half* wqt; cudaGetSymbolAddress((void**)&wqt, g_wqt);
    __half* wkt; cudaGetSymbolAddress((void**)&wkt, g_wkt);
    __half* wvt; cudaGetSymbolAddress((void**)&wvt, g_wvt);
    __half* wot; cudaGetSymbolAddress((void**)&wot, g_wot);
    __half* hh;  cudaGetSymbolAddress((void**)&hh, g_hh);
    __half* hl;  cudaGetSymbolAddress((void**)&hl, g_hl);
    __half* oh;  cudaGetSymbolAddress((void**)&oh, g_oh);
    __half* ol;  cudaGetSymbolAddress((void**)&ol, g_ol);

    cudaFuncSetAttribute(hgemm3, cudaFuncAttributeMaxDynamicSharedMemorySize,
                         GEMM_SMEM_BYTES);
    cudaFuncSetAttribute(attn_mma, cudaFuncAttributeMaxDynamicSharedMemorySize,
                         ATTN_SMEM_BYTES);

    // 0: split hidden into fp16 hi/lo
    split_hidden<<<(2048 * 4096 / 2 + 255) / 256, 256>>>(hidden, hh, hl,
                                                         2048 * 4096);
    // 1-4: transpose+convert weights to fp16 [N][K]
    convert_w<<<dim3(128, 128), dim3(32, 8)>>>(Wq, wqt, 4096, 4096);
    convert_w<<<dim3(32, 128), dim3(32, 8)>>>(Wk, wkt, 4096, 1024);
    convert_w<<<dim3(32, 128), dim3(32, 8)>>>(Wv, wvt, 4096, 1024);
    convert_w<<<dim3(128, 128), dim3(32, 8)>>>(Wo, wot, 4096, 4096);

    // 5: Q projection (profiled launch)
    hgemm3<<<dim3(32, 16), 256, GEMM_SMEM_BYTES>>>(hh, hl, wqt, q,
                                                   2048, 4096, 4096);
    // 6: rope table
    rope_table<<<(2048 * 64 + 255) / 256, 256>>>(positions);
    // 7-8: K, V projections
    hgemm3<<<dim3(8, 16), 256, GEMM_SMEM_BYTES>>>(hh, hl, wkt, k,
                                                  2048, 1024, 4096);
    hgemm3<<<dim3(8, 16), 256, GEMM_SMEM_BYTES>>>(hh, hl, wvt, v,
                                                  2048, 1024, 4096);
    // 9: fused rmsnorm+rope
    rmsrope_both<<<(2048 * 40) / 8, 256>>>(q, k, q_norm_w, k_norm_w);
    // 10: attention (emits fp16 hi/lo O)
    attn_mma<<<dim3(16, 32), 256, ATTN_SMEM_BYTES>>>(q, k, v, oh, ol);
    // 11: output projection
    hgemm3<<<dim3(32, 16), 256, GEMM_SMEM_BYTES>>>(oh, ol, wot, out,
                                                   2048, 4096, 4096);
}

// round 10
// speedup vs baseline: 1.8409x; 1.0538x over previous
#include <cuda_runtime.h>
#include <cuda_fp16.h>
#include <math.h>
#include <stdint.h>

// ---------------- scratch (device globals: no allocation allowed) ----------
__device__ float g_q[2048 * 4096];
__device__ float g_k[2048 * 1024];
__device__ float g_v[2048 * 1024];
__device__ float g_cos[2048 * 64];
__device__ float g_sin[2048 * 64];
// fp16 pre-converted operands
__device__ __half g_wqt[4096 * 4096];   // Wq^T [N][K]
__device__ __half g_wkt[1024 * 4096];
__device__ __half g_wvt[1024 * 4096];
__device__ __half g_wot[4096 * 4096];   // Wo^T
__device__ __half g_hh[2048 * 4096];    // hidden hi
__device__ __half g_hl[2048 * 4096];    // hidden lo
__device__ __half g_oh[2048 * 4096];    // attn out hi
__device__ __half g_ol[2048 * 4096];    // attn out lo
__device__ __half g_kh[2048 * 1024];    // K after rmsnorm+rope, fp16
__device__ __half g_vt[1024 * 2048];    // V transposed [channel][token] fp16

// ==================== shared helpers =======================================
__device__ __forceinline__ void mma16816(float acc[4], const uint32_t a[4],
                                         const uint32_t b[2]) {
    asm("mma.sync.aligned.m16n8k16.row.col.f32.f16.f16.f32 "
        "{%0,%1,%2,%3}, {%4,%5,%6,%7}, {%8,%9}, {%0,%1,%2,%3};\n"
        : "+f"(acc[0]), "+f"(acc[1]), "+f"(acc[2]), "+f"(acc[3])
        : "r"(a[0]), "r"(a[1]), "r"(a[2]), "r"(a[3]), "r"(b[0]), "r"(b[1]));
}

__device__ __forceinline__ void ldsm_x4(uint32_t& r0, uint32_t& r1,
                                        uint32_t& r2, uint32_t& r3,
                                        uint32_t addr) {
    asm volatile(
        "ldmatrix.sync.aligned.m8n8.x4.shared.b16 {%0,%1,%2,%3}, [%4];"
        : "=r"(r0), "=r"(r1), "=r"(r2), "=r"(r3) : "r"(addr));
}

__device__ __forceinline__ uint32_t smem_u32(const void* p) {
    uint32_t a;
    asm("{ .reg .u64 t; cvta.to.shared.u64 t, %1; cvt.u32.u64 %0, t; }"
        : "=r"(a) : "l"(p));
    return a;
}

__device__ __forceinline__ void cp16(uint32_t smem, const void* g) {
    asm volatile("cp.async.cg.shared.global [%0], [%1], 16;\n"
                 :: "r"(smem), "l"(g) : "memory");
}
#define CP_COMMIT asm volatile("cp.async.commit_group;\n" ::: "memory")
#define CP_WAIT1 asm volatile("cp.async.wait_group 1;\n" ::: "memory")

// fp16 exact split: x = hi + lo (~24 bits)
__device__ __forceinline__ void splitA2(float x, float y, uint32_t& hi, uint32_t& lo) {
    __half hx = __float2half_rn(x);
    __half hy = __float2half_rn(y);
    __half lx = __float2half_rn(x - __half2float(hx));
    __half ly = __float2half_rn(y - __half2float(hy));
    __half2 h = __halves2half2(hx, hy);
    __half2 l = __halves2half2(lx, ly);
    hi = *(uint32_t*)&h;
    lo = *(uint32_t*)&l;
}

// ==================== conversion kernels ===================================
__global__ void convert_w(const float* __restrict__ W, __half* __restrict__ Wt,
                          int K, int N) {
    __shared__ float t[32][33];
    int n0 = blockIdx.x * 32, k0 = blockIdx.y * 32;
    int tx = threadIdx.x, ty = threadIdx.y;   // 32 x 8
#pragma unroll
    for (int i = 0; i < 32; i += 8)
        t[ty + i][tx] = W[(size_t)(k0 + ty + i) * N + n0 + tx];
    __syncthreads();
#pragma unroll
    for (int i = 0; i < 32; i += 8)
        Wt[(size_t)(n0 + ty + i) * K + k0 + tx] = __float2half_rn(t[tx][ty + i]);
}

__global__ void split_hidden(const float* __restrict__ H, __half* __restrict__ Hh,
                             __half* __restrict__ Hl, int n) {
    int i = (blockIdx.x * blockDim.x + threadIdx.x) * 2;
    if (i >= n) return;
    float2 v = *(const float2*)(H + i);
    uint32_t h, l;
    splitA2(v.x, v.y, h, l);
    *(uint32_t*)(Hh + i) = h;
    *(uint32_t*)(Hl + i) = l;
}

// V fp32 [2048 tok][1024 ch] -> Vt fp16 [1024 ch][2048 tok]
__global__ void convert_vt(const float* __restrict__ V, __half* __restrict__ Vt) {
    __shared__ float t[32][33];
    int tok0 = blockIdx.x * 32, ch0 = blockIdx.y * 32;
    int tx = threadIdx.x, ty = threadIdx.y;   // 32 x 8
#pragma unroll
    for (int i = 0; i < 32; i += 8)
        t[ty + i][tx] = V[(size_t)(tok0 + ty + i) * 1024 + ch0 + tx];
    __syncthreads();
#pragma unroll
    for (int i = 0; i < 32; i += 8)
        Vt[(size_t)(ch0 + ty + i) * 2048 + tok0 + tx] = __float2half_rn(t[tx][ty + i]);
}

// ==================== fp16 cp.async tensor-core GEMM core ==================
#define KPAD 40
#define TILE_HALFS (128 * KPAD)
#define BUF3 (3 * TILE_HALFS)              // Ah, Al, B
#define GEMM_SMEM_BYTES (2 * BUF3 * 2)

__device__ __forceinline__ void gemm_core(const __half* __restrict__ Ah,
                                          const __half* __restrict__ Al,
                                          const __half* __restrict__ Bt,
                                          float* __restrict__ C,
                                          int N, int K, int bx, int by,
                                          __half* smbuf) {
    const int tid = threadIdx.x;
    const int lane = tid & 31;
    const int w = tid >> 5;
    const int wm = w >> 1;
    const int wn = w & 1;
    const int g = lane >> 2;
    const int cc = lane & 3;
    const int quad = lane >> 3;
    const int qr = lane & 7;

    const __half* Abh = Ah + (size_t)by * 128 * K;
    const __half* Abl = Al + (size_t)by * 128 * K;
    const __half* Bb = Bt + (size_t)bx * 128 * K;

    const uint32_t smbase = smem_u32(smbuf);

    const int crow = tid >> 1;
    const int cseg = (tid & 1) * 32;

    auto issue = [&](int buf, int k0) {
        uint32_t dst = smbase + buf * BUF3 * 2 + crow * 80 + cseg;
        const char* sa = (const char*)(Abh + (size_t)crow * K + k0) + cseg;
        cp16(dst, sa);
        cp16(dst + 16, sa + 16);
        const char* sl = (const char*)(Abl + (size_t)crow * K + k0) + cseg;
        cp16(dst + TILE_HALFS * 2, sl);
        cp16(dst + TILE_HALFS * 2 + 16, sl + 16);
        const char* sb = (const char*)(Bb + (size_t)crow * K + k0) + cseg;
        cp16(dst + 2 * TILE_HALFS * 2, sb);
        cp16(dst + 2 * TILE_HALFS * 2 + 16, sb + 16);
    };

    float acc[2][8][4];
#pragma unroll
    for (int tm = 0; tm < 2; tm++)
#pragma unroll
        for (int tn = 0; tn < 8; tn++)
#pragma unroll
            for (int j = 0; j < 4; j++) acc[tm][tn][j] = 0.f;

    const uint32_t aLaneOff =
        (uint32_t)((wm * 32 + (quad & 1) * 8 + qr) * KPAD + (quad >> 1) * 8) * 2;
    const uint32_t bLaneOff =
        (uint32_t)((wn * 64 + (quad >> 1) * 8 + qr) * KPAD + (quad & 1) * 8) * 2;

    auto mma_tile = [&](int buf) {
        const uint32_t sAh = smbase + buf * BUF3 * 2;
        const uint32_t sAl = sAh + TILE_HALFS * 2;
        const uint32_t sBh = sAh + 2 * TILE_HALFS * 2;
#pragma unroll
        for (int ks = 0; ks < 32; ks += 16) {
            uint32_t ah[2][4], al[2][4];
#pragma unroll
            for (int tm = 0; tm < 2; tm++) {
                uint32_t off = aLaneOff + (uint32_t)(tm * 16 * KPAD + ks) * 2;
                ldsm_x4(ah[tm][0], ah[tm][1], ah[tm][2], ah[tm][3], sAh + off);
                ldsm_x4(al[tm][0], al[tm][1], al[tm][2], al[tm][3], sAl + off);
            }
            uint32_t bh[4][4];
#pragma unroll
            for (int tp = 0; tp < 4; tp++) {
                uint32_t off = bLaneOff + (uint32_t)(tp * 16 * KPAD + ks) * 2;
                ldsm_x4(bh[tp][0], bh[tp][1], bh[tp][2], bh[tp][3], sBh + off);
            }
#pragma unroll
            for (int tp = 0; tp < 4; tp++)
#pragma unroll
                for (int half = 0; half < 2; half++)
#pragma unroll
                    for (int tm = 0; tm < 2; tm++)
                        mma16816(acc[tm][tp * 2 + half], ah[tm], &bh[tp][half * 2]);
#pragma unroll
            for (int tp = 0; tp < 4; tp++)
#pragma unroll
                for (int half = 0; half < 2; half++)
#pragma unroll
                    for (int tm = 0; tm < 2; tm++)
                        mma16816(acc[tm][tp * 2 + half], al[tm], &bh[tp][half * 2]);
        }
    };

    const int ntiles = K / 32;

    issue(0, 0);
    CP_COMMIT;
    issue(1, 32);
    CP_COMMIT;

    for (int t = 0; t < ntiles; t++) {
        CP_WAIT1;
        __syncthreads();
        mma_tile(t & 1);
        __syncthreads();
        if (t + 2 < ntiles) issue(t & 1, (t + 2) * 32);
        CP_COMMIT;
    }

#pragma unroll
    for (int tm = 0; tm < 2; tm++) {
        int row0 = by * 128 + wm * 32 + tm * 16 + g;
#pragma unroll
        for (int tn = 0; tn < 8; tn++) {
            int col = bx * 128 + wn * 64 + tn * 8 + 2 * cc;
            *(float2*)(C + (size_t)row0 * N + col) =
                make_float2(acc[tm][tn][0], acc[tm][tn][1]);
            *(float2*)(C + (size_t)(row0 + 8) * N + col) =
                make_float2(acc[tm][tn][2], acc[tm][tn][3]);
        }
    }
}

__global__ __launch_bounds__(256, 2) void hgemm3(const __half* __restrict__ Ah,
                                                 const __half* __restrict__ Al,
                                                 const __half* __restrict__ Bt,
                                                 float* __restrict__ C,
                                                 int N, int K) {
    extern __shared__ __half smbuf[];
    gemm_core(Ah, Al, Bt, C, N, K, blockIdx.x, blockIdx.y, smbuf);
}

// K and V projections merged: one wave of 256 CTAs.
__global__ __launch_bounds__(256, 2) void hgemm3_kv(const __half* __restrict__ Ah,
                                                    const __half* __restrict__ Al,
                                                    const __half* __restrict__ Bk,
                                                    const __half* __restrict__ Bv,
                                                    float* __restrict__ Ck,
                                                    float* __restrict__ Cv,
                                                    int K) {
    extern __shared__ __half smbuf[];
    if (blockIdx.z == 0)
        gemm_core(Ah, Al, Bk, Ck, 1024, K, blockIdx.x, blockIdx.y, smbuf);
    else
        gemm_core(Ah, Al, Bv, Cv, 1024, K, blockIdx.x, blockIdx.y, smbuf);
}

// ---------------- RoPE cos/sin table (fp64 for phase accuracy) -------------
__global__ void rope_table(const int* __restrict__ positions) {
    int idx = blockIdx.x * blockDim.x + threadIdx.x;
    if (idx >= 2048 * 64) return;
    int t = idx >> 6;
    int j = idx & 63;
    double inv = exp(-(double)j * (log(1.0e6) / 64.0));
    double f = (double)positions[t] * inv;
    g_cos[idx] = (float)cos(f);
    g_sin[idx] = (float)sin(f);
}

// ---------------- fused RMSNorm + RoPE; K written directly as fp16 ---------
__global__ void rmsrope_both(float* __restrict__ Q, const float* __restrict__ Kin,
                             __half* __restrict__ Kout,
                             const float* __restrict__ qw,
                             const float* __restrict__ kw) {
    int wg = (blockIdx.x * blockDim.x + threadIdx.x) >> 5;
    int lane = threadIdx.x & 31;

    const float* x;
    int t;
    const float* w;
    bool isQ;
    float* xq = 0;
    __half* xk = 0;
    if (wg < 2048 * 32) {
        t = wg >> 5;
        int h = wg & 31;
        xq = Q + (size_t)t * 4096 + h * 128;
        x = xq;
        w = qw;
        isQ = true;
    } else {
        int wg2 = wg - 2048 * 32;
        if (wg2 >= 2048 * 8) return;
        t = wg2 >> 3;
        int h = wg2 & 7;
        x = Kin + (size_t)t * 1024 + h * 128;
        xk = Kout + (size_t)t * 1024 + h * 128;
        w = kw;
        isQ = false;
    }

    float v0 = x[lane], v1 = x[lane + 32], v2 = x[lane + 64], v3 = x[lane + 96];
    float ss = v0 * v0 + v1 * v1 + v2 * v2 + v3 * v3;
#pragma unroll
    for (int off = 16; off > 0; off >>= 1) ss += __shfl_xor_sync(0xffffffffu, ss, off);
    float rms = rsqrtf(ss * (1.f / 128.f) + 1e-6f);

    v0 *= rms * w[lane];
    v1 *= rms * w[lane + 32];
    v2 *= rms * w[lane + 64];
    v3 *= rms * w[lane + 96];

    float c0 = g_cos[t * 64 + lane],      s0 = g_sin[t * 64 + lane];
    float c1 = g_cos[t * 64 + lane + 32], s1 = g_sin[t * 64 + lane + 32];

    float r0 = v0 * c0 - v2 * s0;
    float r2 = v2 * c0 + v0 * s0;
    float r1 = v1 * c1 - v3 * s1;
    float r3 = v3 * c1 + v1 * s1;

    if (isQ) {
        xq[lane] = r0;
        xq[lane + 64] = r2;
        xq[lane + 32] = r1;
        xq[lane + 96] = r3;
    } else {
        xk[lane] = __float2half_rn(r0);
        xk[lane + 64] = __float2half_rn(r2);
        xk[lane + 32] = __float2half_rn(r1);
        xk[lane + 96] = __float2half_rn(r3);
    }
}

// ==================== tensor-core causal flash attention ===================
// Q fp32 in (split hi/lo in smem); K, V^T pre-converted fp16 in gmem,
// streamed via double-buffered cp.async. O emitted as fp16 hi/lo.
#define DPAD 136
#define VPAD 72
#define AQ_HALFS (128 * DPAD)
#define KBUF_HALFS (64 * DPAD)
#define VBUF_HALFS (128 * VPAD)
#define ATTN_SMEM_BYTES ((2 * AQ_HALFS + 2 * KBUF_HALFS + 2 * VBUF_HALFS) * 2)

__global__ __launch_bounds__(256) void attn_mma(const float* __restrict__ Q,
                                                const __half* __restrict__ Kg,
                                                const __half* __restrict__ Vtg,
                                                __half* __restrict__ Oh,
                                                __half* __restrict__ Ol) {
    extern __shared__ __half asm_buf[];
    __half* Qh = asm_buf;
    __half* Ql = Qh + AQ_HALFS;
    __half* Kb = Ql + AQ_HALFS;                // 2 buffers
    __half* Vb = Kb + 2 * KBUF_HALFS;          // 2 buffers

    const uint32_t sQh = smem_u32(Qh);
    const uint32_t sQl = smem_u32(Ql);
    const uint32_t sK0 = smem_u32(Kb);
    const uint32_t sV0 = smem_u32(Vb);

    const int qbi = 15 - blockIdx.x;
    const int h = blockIdx.y;
    const int kvh = h >> 2;
    const int tid = threadIdx.x;
    const int lane = tid & 31;
    const int w = tid >> 5;
    const int g = lane >> 2;
    const int cc = lane & 3;
    const int quad = lane >> 3;
    const int qr = lane & 7;

    const int ntiles = 2 * (qbi + 1);
    const float scale = 0.08838834764831845f;

    // ---- load Q block (128 x 128), split hi/lo ----
    {
        const int row = tid >> 1;
        const int half = tid & 1;
        const float* qp = Q + (size_t)(qbi * 128 + row) * 4096 + h * 128 + half * 64;
#pragma unroll
        for (int i = 0; i < 32; i++) {
            float2 v = *(const float2*)(qp + 2 * i);
            uint32_t hh, ll;
            splitA2(v.x, v.y, hh, ll);
            int off = row * DPAD + half * 64 + 2 * i;
            *(uint32_t*)&Qh[off] = hh;
            *(uint32_t*)&Ql[off] = ll;
        }
    }

    // cp.async mapping for K / Vt tiles
    const int krow = tid >> 2;                 // 0..63
    const int kc0 = (tid & 3) * 16;
    const int vrow = tid >> 1;                 // 0..127
    const int vc0 = (tid & 1) * 16;

    auto issue_kv = [&](int kb, int buf) {
        const char* ks = (const char*)(Kg + (size_t)(kb * 64 + krow) * 1024 + kvh * 128);
        uint32_t kd = sK0 + buf * KBUF_HALFS * 2 + krow * (DPAD * 2);
#pragma unroll
        for (int i = 0; i < 4; i++)
            cp16(kd + kc0 + i * 64, ks + kc0 + i * 64);
        const char* vs = (const char*)(Vtg + (size_t)(kvh * 128 + vrow) * 2048 + kb * 64);
        uint32_t vd = sV0 + buf * VBUF_HALFS * 2 + vrow * (VPAD * 2);
#pragma unroll
        for (int i = 0; i < 4; i++)
            cp16(vd + vc0 + i * 32, vs + vc0 + i * 32);
    };

    const uint32_t aQOff =
        (uint32_t)((w * 16 + (quad & 1) * 8 + qr) * DPAD + (quad >> 1) * 8) * 2;
    const uint32_t bKOff =
        (uint32_t)(((quad >> 1) * 8 + qr) * DPAD + (quad & 1) * 8) * 2;
    const uint32_t bVOff =
        (uint32_t)(((quad >> 1) * 8 + qr) * VPAD + (quad & 1) * 8) * 2;

    float oacc[16][4];
#pragma unroll
    for (int tn = 0; tn < 16; tn++)
#pragma unroll
        for (int j = 0; j < 4; j++) oacc[tn][j] = 0.f;

    float mA = -1e30f, mB = -1e30f, lA = 0.f, lB = 0.f;
    const int rowA = qbi * 128 + w * 16 + g;
    const int rowB = rowA + 8;

    issue_kv(0, 0);
    CP_COMMIT;
    __syncthreads();   // Q smem ready (and tile 0 in flight)

    for (int kb = 0; kb < ntiles; kb++) {
        if (kb + 1 < ntiles) issue_kv(kb + 1, (kb + 1) & 1);
        CP_COMMIT;
        CP_WAIT1;
        __syncthreads();

        const uint32_t sKh = sK0 + (kb & 1) * KBUF_HALFS * 2;
        const uint32_t sVh = sV0 + (kb & 1) * VBUF_HALFS * 2;

        // ---- S = Q K^T, 2-pass ----
        float sacc[8][4];
#pragma unroll
        for (int tn = 0; tn < 8; tn++)
#pragma unroll
            for (int j = 0; j < 4; j++) sacc[tn][j] = 0.f;

#pragma unroll
        for (int ks = 0; ks < 128; ks += 16) {
            uint32_t ah[4], al[4];
            uint32_t aoff = aQOff + (uint32_t)ks * 2;
            ldsm_x4(ah[0], ah[1], ah[2], ah[3], sQh + aoff);
            ldsm_x4(al[0], al[1], al[2], al[3], sQl + aoff);
            uint32_t bh[4][4];
#pragma unroll
            for (int p = 0; p < 4; p++) {
                uint32_t boff = bKOff + (uint32_t)(p * 16 * DPAD + ks) * 2;
                ldsm_x4(bh[p][0], bh[p][1], bh[p][2], bh[p][3], sKh + boff);
            }
#pragma unroll
            for (int p = 0; p < 4; p++)
#pragma unroll
                for (int half = 0; half < 2; half++)
                    mma16816(sacc[2 * p + half], ah, &bh[p][half * 2]);
#pragma unroll
            for (int p = 0; p < 4; p++)
#pragma unroll
                for (int half = 0; half < 2; half++)
                    mma16816(sacc[2 * p + half], al, &bh[p][half * 2]);
        }

        // ---- softmax on fragments ----
        float mxA = -1e30f, mxB = -1e30f;
#pragma unroll
        for (int tn = 0; tn < 8; tn++) {
            int colbase = kb * 64 + tn * 8 + 2 * cc;
            float s0 = sacc[tn][0] * scale;
            float s1 = sacc[tn][1] * scale;
            float s2 = sacc[tn][2] * scale;
            float s3 = sacc[tn][3] * scale;
            if (colbase > rowA) s0 = -1e30f;
            if (colbase + 1 > rowA) s1 = -1e30f;
            if (colbase > rowB) s2 = -1e30f;
            if (colbase + 1 > rowB) s3 = -1e30f;
            sacc[tn][0] = s0; sacc[tn][1] = s1;
            sacc[tn][2] = s2; sacc[tn][3] = s3;
            mxA = fmaxf(mxA, fmaxf(s0, s1));
            mxB = fmaxf(mxB, fmaxf(s2, s3));
        }
        mxA = fmaxf(mxA, __shfl_xor_sync(0xffffffffu, mxA, 1));
        mxA = fmaxf(mxA, __shfl_xor_sync(0xffffffffu, mxA, 2));
        mxB = fmaxf(mxB, __shfl_xor_sync(0xffffffffu, mxB, 1));
        mxB = fmaxf(mxB, __shfl_xor_sync(0xffffffffu, mxB, 2));

        float mnA = fmaxf(mA, mxA);
        float mnB = fmaxf(mB, mxB);
        float corrA = __expf(mA - mnA);
        float corrB = __expf(mB - mnB);
        mA = mnA;
        mB = mnB;

        float sumA = 0.f, sumB = 0.f;
#pragma unroll
        for (int tn = 0; tn < 8; tn++) {
            float p0 = __expf(sacc[tn][0] - mnA);
            float p1 = __expf(sacc[tn][1] - mnA);
            float p2 = __expf(sacc[tn][2] - mnB);
            float p3 = __expf(sacc[tn][3] - mnB);
            sacc[tn][0] = p0; sacc[tn][1] = p1;
            sacc[tn][2] = p2; sacc[tn][3] = p3;
            sumA += p0 + p1;
            sumB += p2 + p3;
        }
        sumA += __shfl_xor_sync(0xffffffffu, sumA, 1);
        sumA += __shfl_xor_sync(0xffffffffu, sumA, 2);
        sumB += __shfl_xor_sync(0xffffffffu, sumB, 1);
        sumB += __shfl_xor_sync(0xffffffffu, sumB, 2);
        lA = lA * corrA + sumA;
        lB = lB * corrB + sumB;

#pragma unroll
        for (int tn = 0; tn < 16; tn++) {
            oacc[tn][0] *= corrA;
            oacc[tn][1] *= corrA;
            oacc[tn][2] *= corrB;
            oacc[tn][3] *= corrB;
        }

        // ---- O += P V, 2-pass (P exact, V hi only) ----
#pragma unroll
        for (int j = 0; j < 4; j++) {
            uint32_t pah[4], pal[4];
            splitA2(sacc[2 * j][0], sacc[2 * j][1], pah[0], pal[0]);
            splitA2(sacc[2 * j][2], sacc[2 * j][3], pah[1], pal[1]);
            splitA2(sacc[2 * j + 1][0], sacc[2 * j + 1][1], pah[2], pal[2]);
            splitA2(sacc[2 * j + 1][2], sacc[2 * j + 1][3], pah[3], pal[3]);
#pragma unroll
            for (int pp = 0; pp < 4; pp++) {
                uint32_t bh[2][4];
#pragma unroll
                for (int i = 0; i < 2; i++) {
                    uint32_t voff = bVOff +
                        (uint32_t)((2 * pp + i) * 16 * VPAD + j * 16) * 2;
                    ldsm_x4(bh[i][0], bh[i][1], bh[i][2], bh[i][3], sVh + voff);
                }
#pragma unroll
                for (int i = 0; i < 2; i++)
#pragma unroll
                    for (int half = 0; half < 2; half++)
                        mma16816(oacc[2 * (2 * pp + i) + half], pah, &bh[i][half * 2]);
#pragma unroll
                for (int i = 0; i < 2; i++)
#pragma unroll
                    for (int half = 0; half < 2; half++)
                        mma16816(oacc[2 * (2 * pp + i) + half], pal, &bh[i][half * 2]);
            }
        }
        __syncthreads();
    }

    // ---- epilogue: write O as fp16 hi/lo split ----
    const float invA = 1.f / lA;
    const float invB = 1.f / lB;
#pragma unroll
    for (int tn = 0; tn < 16; tn++) {
        int d = tn * 8 + 2 * cc;
        uint32_t hh, ll;
        splitA2(oacc[tn][0] * invA, oacc[tn][1] * invA, hh, ll);
        *(uint32_t*)(Oh + (size_t)rowA * 4096 + h * 128 + d) = hh;
        *(uint32_t*)(Ol + (size_t)rowA * 4096 + h * 128 + d) = ll;
        splitA2(oacc[tn][2] * invB, oacc[tn][3] * invB, hh, ll);
        *(uint32_t*)(Oh + (size_t)rowB * 4096 + h * 128 + d) = hh;
        *(uint32_t*)(Ol + (size_t)rowB * 4096 + h * 128 + d) = ll;
    }
}

// ---------------- launch ----------------------------------------------------
extern "C" void kernel_launch(void* const* d_in, const int* in_sizes, int n_in,
                              void* d_out, int out_size) {
    const float* hidden    = (const float*)d_in[0];
    const int*   positions = (const int*)d_in[1];
    const float* Wq        = (const float*)d_in[2];
    const float* Wk        = (const float*)d_in[3];
    const float* Wv        = (const float*)d_in[4];
    const float* Wo        = (const float*)d_in[5];
    const float* q_norm_w  = (const float*)d_in[6];
    const float* k_norm_w  = (const float*)d_in[7];
    float* out = (float*)d_out;

    float* q;  cudaGetSymbolAddress((void**)&q, g_q);
    float* k;  cudaGetSymbolAddress((void**)&k, g_k);
    float* v;  cudaGetSymbolAddress((void**)&v, g_v);
    __half* wqt; cudaGetSymbolAddress((void**)&wqt, g_wqt);
    __half* wkt; cudaGetSymbolAddress((void**)&wkt, g_wkt);
    __half* wvt; cudaGetSymbolAddress((void**)&wvt, g_wvt);
    __half* wot; cudaGetSymbolAddress((void**)&wot, g_wot);
    __half* hh;  cudaGetSymbolAddress((void**)&hh, g_hh);
    __half* hl;  cudaGetSymbolAddress((void**)&hl, g_hl);
    __half* oh;  cudaGetSymbolAddress((void**)&oh, g_oh);
    __half* ol;  cudaGetSymbolAddress((void**)&ol, g_ol);
    __half* kh;  cudaGetSymbolAddress((void**)&kh, g_kh);
    __half* vt;  cudaGetSymbolAddress((void**)&vt, g_vt);

    cudaFuncSetAttribute(hgemm3, cudaFuncAttributeMaxDynamicSharedMemorySize,
                         GEMM_SMEM_BYTES);
    cudaFuncSetAttribute(hgemm3_kv, cudaFuncAttributeMaxDynamicSharedMemorySize,
                         GEMM_SMEM_BYTES);
    cudaFuncSetAttribute(attn_mma, cudaFuncAttributeMaxDynamicSharedMemorySize,
                         ATTN_SMEM_BYTES);

    // 0: split hidden into fp16 hi/lo
    split_hidden<<<(2048 * 4096 / 2 + 255) / 256, 256>>>(hidden, hh, hl,
                                                         2048 * 4096);
    // 1-4: transpose+convert weights to fp16 [N][K]
    convert_w<<<dim3(128, 128), dim3(32, 8)>>>(Wq, wqt, 4096, 4096);
    convert_w<<<dim3(32, 128), dim3(32, 8)>>>(Wk, wkt, 4096, 1024);
    convert_w<<<dim3(32, 128), dim3(32, 8)>>>(Wv, wvt, 4096, 1024);
    convert_w<<<dim3(128, 128), dim3(32, 8)>>>(Wo, wot, 4096, 4096);

    // 5: Q projection
    hgemm3<<<dim3(32, 16), 256, GEMM_SMEM_BYTES>>>(hh, hl, wqt, q, 4096, 4096);
    // 6: rope table
    rope_table<<<(2048 * 64 + 255) / 256, 256>>>(positions);
    // 7: K + V projections in one wave
    hgemm3_kv<<<dim3(8, 16, 2), 256, GEMM_SMEM_BYTES>>>(hh, hl, wkt, wvt,
                                                        k, v, 4096);
    // 8: V transpose + fp16 convert
    convert_vt<<<dim3(64, 32), dim3(32, 8)>>>(v, vt);
    // 9: fused rmsnorm+rope (K emitted fp16)
    rmsrope_both<<<(2048 * 40) / 8, 256>>>(q, k, kh, q_norm_w, k_norm_w);
    // 10: attention
    attn_mma<<<dim3(16, 32), 256, ATTN_SMEM_BYTES>>>(q, kh, vt, oh, ol);
    // 11: output projection
    hgemm3<<<dim3(32, 16), 256, GEMM_SMEM_BYTES>>>(oh, ol, wot, out, 4096, 4096);
}